// round 8
// baseline (speedup 1.0000x reference)
#include <cuda_runtime.h>
#include <cuda_fp16.h>
#include <cfloat>
#include <math.h>
#include <stdint.h>

// Problem constants
#define BATCH 8
#define SEQ   1024
#define DIM   1024
#define NHEAD 16
#define HDIM  64
#define FDIM  4096
#define TOK   (BATCH*SEQ)   // 8192

// ---------------- scratch (static device globals; no allocation) ----------------
__device__ __half g_ln  [(size_t)TOK * DIM];    // LN out (half, feeds GEMM)
__device__ float  g_ln32[(size_t)TOK * DIM];    // LN1 fp32 copy (FFN2 residual)
__device__ float  g_qkv [(size_t)TOK * 3*DIM];  // qkv (fp32 — feeds fp32 attention)
__device__ __half g_att [(size_t)TOK * DIM];    // attention out (half)
__device__ float  g_x   [(size_t)TOK * DIM];    // src + proj(att) (fp32)
__device__ __half g_ffn [(size_t)TOK * FDIM];   // GELU(FFN1) (half)
__device__ int    g_msk [TOK];
// half weight copies
__device__ __half g_wq[(size_t)3*DIM*DIM];
__device__ __half g_wp[(size_t)DIM*DIM];
__device__ __half g_w1[(size_t)FDIM*DIM];
__device__ __half g_w2[(size_t)DIM*FDIM];

// ======================= small helpers =======================
__device__ __forceinline__ uint32_t smem_u32(const void* p) {
    uint32_t a;
    asm("{ .reg .u64 t; cvta.to.shared.u64 t, %1; cvt.u32.u64 %0, t; }" : "=r"(a) : "l"(p));
    return a;
}

__device__ __forceinline__ void mma_f16(float c[4],
                                        uint32_t a0, uint32_t a1, uint32_t a2, uint32_t a3,
                                        uint32_t b0, uint32_t b1) {
    asm volatile(
        "mma.sync.aligned.m16n8k16.row.col.f32.f16.f16.f32 "
        "{%0,%1,%2,%3}, {%4,%5,%6,%7}, {%8,%9}, {%0,%1,%2,%3};"
        : "+f"(c[0]), "+f"(c[1]), "+f"(c[2]), "+f"(c[3])
        : "r"(a0), "r"(a1), "r"(a2), "r"(a3), "r"(b0), "r"(b1));
}

#define CP_ASYNC16(saddr, gptr) \
    asm volatile("cp.async.cg.shared.global [%0], [%1], 16;" :: "r"(saddr), "l"(gptr))
#define CP_COMMIT() asm volatile("cp.async.commit_group;")
#define CP_WAIT1()  asm volatile("cp.async.wait_group 1;")
#define CP_WAIT0()  asm volatile("cp.async.wait_group 0;")

__device__ __forceinline__ float gelu_f(float x)
{
    return 0.5f * x * (1.0f + erff(x * 0.70710678118654752f));
}

// ---------------- fp32 -> fp16 weight conversion ----------------
__global__ void cvt_h_kernel(const float4* __restrict__ in, __half2* __restrict__ out, int n4)
{
    int i = blockIdx.x * blockDim.x + threadIdx.x;
    if (i < n4) {
        float4 v = in[i];
        out[2*i]   = __floats2half2_rn(v.x, v.y);
        out[2*i+1] = __floats2half2_rn(v.z, v.w);
    }
}

// ---------------- mask dtype detection + normalization ----------------
__global__ void mask_kernel(const unsigned char* __restrict__ raw, int* __restrict__ gm)
{
    __shared__ int cnt[4];
    int t = threadIdx.x;
    if (t < 4) cnt[t] = 0;
    __syncthreads();
    int l1=0, l2=0, l3=0, lb=0;
    for (int i = t; i < TOK; i += blockDim.x) {
        unsigned char bch = raw[i];
        if (bch) {
            int m = i & 3;
            if (m == 1) l1++;
            else if (m == 2) l2++;
            else if (m == 3) l3++;
            if (bch > 1) lb++;
        }
    }
    atomicAdd(&cnt[0], l1); atomicAdd(&cnt[1], l2);
    atomicAdd(&cnt[2], l3); atomicAdd(&cnt[3], lb);
    __syncthreads();
    int c1 = cnt[0], c2 = cnt[1], c3 = cnt[2], cb = cnt[3];
    int type;
    if (c1 < 64 && c2 < 64 && c3 < 64) type = 0;
    else if (c1 < 64)                  type = 1;
    else if (cb < 64)                  type = 2;
    else                               type = 3;
    for (int i = t; i < TOK; i += blockDim.x) {
        int v;
        if      (type == 0) v = (((const int*)raw)[i] != 0);
        else if (type == 1) v = (((const float*)raw)[i] != 0.0f);
        else if (type == 2) v = (raw[i] != 0);
        else                v = (((const unsigned short*)raw)[i] != 0);
        gm[i] = v;
    }
}

// ---------------- LayerNorm: half out (+ optional fp32 copy) ----------------
template<bool WF>
__global__ void ln_kernel(const float* __restrict__ in,
                          const float* __restrict__ gamma,
                          const float* __restrict__ beta,
                          __half* __restrict__ outh,
                          float* __restrict__ outf)
{
    int row = blockIdx.x;
    int t = threadIdx.x;
    const float* xr = in + (size_t)row * DIM;
    float4 v = ((const float4*)xr)[t];
    float s = v.x + v.y + v.z + v.w;
    float q = v.x*v.x + v.y*v.y + v.z*v.z + v.w*v.w;
    #pragma unroll
    for (int o = 16; o; o >>= 1) {
        s += __shfl_xor_sync(0xffffffffu, s, o);
        q += __shfl_xor_sync(0xffffffffu, q, o);
    }
    __shared__ float ss[8], qq[8];
    if ((t & 31) == 0) { ss[t >> 5] = s; qq[t >> 5] = q; }
    __syncthreads();
    s = 0.f; q = 0.f;
    #pragma unroll
    for (int i = 0; i < 8; i++) { s += ss[i]; q += qq[i]; }
    float mean = s * (1.0f / DIM);
    float var  = q * (1.0f / DIM) - mean * mean;
    float rstd = rsqrtf(var + 1e-5f);
    float4 gv = ((const float4*)gamma)[t];
    float4 bv = ((const float4*)beta)[t];
    float ox = (v.x - mean) * rstd * gv.x + bv.x;
    float oy = (v.y - mean) * rstd * gv.y + bv.y;
    float oz = (v.z - mean) * rstd * gv.z + bv.z;
    float ow = (v.w - mean) * rstd * gv.w + bv.w;
    __half2* oh = (__half2*)(outh + (size_t)row * DIM);
    oh[2*t]   = __floats2half2_rn(ox, oy);
    oh[2*t+1] = __floats2half2_rn(oz, ow);
    if (WF) {
        float4 o = {ox, oy, oz, ow};
        ((float4*)(outf + (size_t)row * DIM))[t] = o;
    }
}

// ======================= FP16 mma.sync GEMM =======================
// C[M,N] = A[M,K] @ B[N,K]^T (+bias/gelu/res). A,B half. 128x128x32 tile,
// 256 threads = 8 warps (2m x 4n), warp tile 64x32, m16n8k16.
#define SH2 20
#define HSTG (128*SH2)                    // half2 per matrix per stage (2560)
#define GSMEM_BYTES (4*HSTG*4)            // 40960

template<int N, int K, bool HAS_BIAS, bool HAS_GELU, bool HAS_RES, bool OUT_HALF>
__global__ void __launch_bounds__(256, 2)
gemm_mma(const __half* __restrict__ A, const __half* __restrict__ Bm,
         const float* __restrict__ bias, const float* __restrict__ res,
         void* __restrict__ Cout)
{
    extern __shared__ __half2 sh[];
    __half2* As[2] = { sh,          sh + HSTG };
    __half2* Bs[2] = { sh + 2*HSTG, sh + 3*HSTG };

    int tid  = threadIdx.x;
    int lane = tid & 31, warp = tid >> 5;
    int wm = warp >> 2, wn = warp & 3;
    int gid = lane >> 2, tig = lane & 3;
    int bm = blockIdx.y * 128, bn = blockIdx.x * 128;

    int lrow = tid >> 2;          // 0..63
    int lseg = tid & 3;           // 0..3

    const __half* gA = A  + (size_t)(bm + lrow) * K + lseg * 8;
    const __half* gB = Bm + (size_t)(bn + lrow) * K + lseg * 8;

    uint32_t sA[2], sB[2];
    #pragma unroll
    for (int st = 0; st < 2; st++) {
        sA[st] = smem_u32(&As[st][lrow*SH2 + lseg*4]);
        sB[st] = smem_u32(&Bs[st][lrow*SH2 + lseg*4]);
    }
    const uint32_t SROW64 = 64u * SH2 * 4u;
    const size_t  GROW64 = (size_t)64 * K;

    int aro[4], bro[4];
    #pragma unroll
    for (int mt = 0; mt < 4; mt++) aro[mt] = (wm*64 + mt*16 + gid)*SH2 + tig;
    #pragma unroll
    for (int nt = 0; nt < 4; nt++) bro[nt] = (wn*32 + nt*8  + gid)*SH2 + tig;

    float acc[4][4][4];
    #pragma unroll
    for (int mt = 0; mt < 4; mt++)
        #pragma unroll
        for (int nt = 0; nt < 4; nt++)
            #pragma unroll
            for (int e = 0; e < 4; e++) acc[mt][nt][e] = 0.f;

    const int KT = K / 32;

    CP_ASYNC16(sA[0], gA); CP_ASYNC16(sA[0] + SROW64, gA + GROW64);
    CP_ASYNC16(sB[0], gB); CP_ASYNC16(sB[0] + SROW64, gB + GROW64);
    CP_COMMIT();

    for (int kt = 0; kt < KT; kt++) {
        int cur = kt & 1;
        if (kt + 1 < KT) {
            int nxt = cur ^ 1;
            size_t go = (size_t)(kt + 1) * 32;
            CP_ASYNC16(sA[nxt], gA + go); CP_ASYNC16(sA[nxt] + SROW64, gA + go + GROW64);
            CP_ASYNC16(sB[nxt], gB + go); CP_ASYNC16(sB[nxt] + SROW64, gB + go + GROW64);
            CP_COMMIT();
            CP_WAIT1();
        } else {
            CP_WAIT0();
        }
        __syncthreads();

        const uint32_t* a_s = (const uint32_t*)As[cur];
        const uint32_t* b_s = (const uint32_t*)Bs[cur];
        #pragma unroll
        for (int ks = 0; ks < 2; ks++) {     // 2 x k16 per BK=32
            int k0 = ks * 8;                 // half2 units
            uint32_t af[4][4];
            #pragma unroll
            for (int mt = 0; mt < 4; mt++) {
                af[mt][0] = a_s[aro[mt] + k0];
                af[mt][1] = a_s[aro[mt] + 8*SH2 + k0];
                af[mt][2] = a_s[aro[mt] + k0 + 4];
                af[mt][3] = a_s[aro[mt] + 8*SH2 + k0 + 4];
            }
            uint32_t bf[4][2];
            #pragma unroll
            for (int nt = 0; nt < 4; nt++) {
                bf[nt][0] = b_s[bro[nt] + k0];
                bf[nt][1] = b_s[bro[nt] + k0 + 4];
            }
            #pragma unroll
            for (int mt = 0; mt < 4; mt++)
                #pragma unroll
                for (int nt = 0; nt < 4; nt++)
                    mma_f16(acc[mt][nt], af[mt][0], af[mt][1], af[mt][2], af[mt][3],
                            bf[nt][0], bf[nt][1]);
        }
        __syncthreads();
    }

    #pragma unroll
    for (int mt = 0; mt < 4; mt++) {
        int row = bm + wm*64 + mt*16 + gid;
        #pragma unroll
        for (int nt = 0; nt < 4; nt++) {
            int col = bn + wn*32 + nt*8 + 2*tig;
            float2 bb = {0.f, 0.f};
            if (HAS_BIAS) bb = *(const float2*)&bias[col];
            #pragma unroll
            for (int half_ = 0; half_ < 2; half_++) {
                int rr = row + half_*8;
                float vx = acc[mt][nt][half_*2+0];
                float vy = acc[mt][nt][half_*2+1];
                if (HAS_BIAS) { vx += bb.x; vy += bb.y; }
                if (HAS_GELU) { vx = gelu_f(vx); vy = gelu_f(vy); }
                if (HAS_RES) {
                    float2 rv = *(const float2*)&res[(size_t)rr * N + col];
                    vx += rv.x; vy += rv.y;
                }
                if (OUT_HALF) {
                    __half2* cp = (__half2*)((__half*)Cout + (size_t)rr * N + col);
                    *cp = __floats2half2_rn(vx, vy);
                } else {
                    float2 o2 = {vx, vy};
                    *(float2*)((float*)Cout + (size_t)rr * N + col) = o2;
                }
            }
        }
    }
}

// ---------------- flash attention, exact softmax, fp32 (verbatim R5, half out) ----------------
#define ATTN_SMEM_FLOATS (3*4096 + 64*65)
#define ATTN_SMEM_BYTES  (ATTN_SMEM_FLOATS*4 + 2*64*4)

__global__ void __launch_bounds__(256)
attn_kernel(const float* __restrict__ qkv, const int* __restrict__ gm,
            __half* __restrict__ outp)
{
    extern __shared__ float smf[];
    float* qsT = smf;
    float* ksT = smf + 4096;
    float* vs  = smf + 8192;
    float* ps  = smf + 12288;
    int*   mq  = (int*)(smf + ATTN_SMEM_FLOATS);
    int*   mk  = mq + 64;

    const float SCALE = 0.125f;
    int tid = threadIdx.x;
    int tx = tid & 15, ty = tid >> 4;
    int bh = blockIdx.y;
    int b  = bh >> 4;
    int h  = bh & 15;
    int q0g = blockIdx.x * 64;

    int r  = tid >> 2;
    int cb = tid & 3;

    {
        const float* qp = qkv + ((size_t)(b*SEQ + q0g + r)) * (3*DIM) + h*HDIM;
        #pragma unroll
        for (int rep = 0; rep < 4; rep++) {
            int c4 = cb + rep*4;
            float4 w = ((const float4*)qp)[c4];
            qsT[(c4*4+0)*64 + r] = w.x;
            qsT[(c4*4+1)*64 + r] = w.y;
            qsT[(c4*4+2)*64 + r] = w.z;
            qsT[(c4*4+3)*64 + r] = w.w;
        }
        if (tid < 64) mq[tid] = gm[b*SEQ + q0g + tid];
    }

    float mrow[4], lrow[4], o_[4][4];
    #pragma unroll
    for (int i = 0; i < 4; i++) {
        mrow[i] = -FLT_MAX; lrow[i] = 0.f;
        #pragma unroll
        for (int j = 0; j < 4; j++) o_[i][j] = 0.f;
    }

    for (int kt = 0; kt < SEQ/64; kt++) {
        __syncthreads();
        int tokbase = b*SEQ + kt*64;
        {
            const float* kp = qkv + ((size_t)(tokbase + r)) * (3*DIM) + DIM   + h*HDIM;
            const float* vp = qkv + ((size_t)(tokbase + r)) * (3*DIM) + 2*DIM + h*HDIM;
            #pragma unroll
            for (int rep = 0; rep < 4; rep++) {
                int c4 = cb + rep*4;
                float4 w = ((const float4*)kp)[c4];
                ksT[(c4*4+0)*64 + r] = w.x;
                ksT[(c4*4+1)*64 + r] = w.y;
                ksT[(c4*4+2)*64 + r] = w.z;
                ksT[(c4*4+3)*64 + r] = w.w;
                float4 u = ((const float4*)vp)[c4];
                ((float4*)(vs + r*64))[c4] = u;
            }
            if (tid < 64) mk[tid] = gm[tokbase + tid];
        }
        __syncthreads();

        float sc[4][4];
        #pragma unroll
        for (int i = 0; i < 4; i++)
            #pragma unroll
            for (int j = 0; j < 4; j++) sc[i][j] = 0.f;
        #pragma unroll 8
        for (int d = 0; d < 64; d++) {
            float4 qa = *(const float4*)&qsT[d*64 + ty*4];
            float4 kb = *(const float4*)&ksT[d*64 + tx*4];
            float av[4] = {qa.x, qa.y, qa.z, qa.w};
            float bv[4] = {kb.x, kb.y, kb.z, kb.w};
            #pragma unroll
            for (int i = 0; i < 4; i++)
                #pragma unroll
                for (int j = 0; j < 4; j++)
                    sc[i][j] += av[i] * bv[j];
        }

        #pragma unroll
        for (int i = 0; i < 4; i++) {
            int qvalid = mq[ty*4 + i];
            float sv[4];
            #pragma unroll
            for (int j = 0; j < 4; j++)
                sv[j] = (qvalid && mk[tx*4 + j]) ? sc[i][j]*SCALE : -FLT_MAX;
            float tm = fmaxf(fmaxf(sv[0], sv[1]), fmaxf(sv[2], sv[3]));
            #pragma unroll
            for (int o = 8; o; o >>= 1)
                tm = fmaxf(tm, __shfl_xor_sync(0xffffffffu, tm, o, 16));
            float mnew = fmaxf(mrow[i], tm);
            float corr = expf(mrow[i] - mnew);
            float p[4], psum = 0.f;
            #pragma unroll
            for (int j = 0; j < 4; j++) { p[j] = expf(sv[j] - mnew); psum += p[j]; }
            #pragma unroll
            for (int o = 8; o; o >>= 1)
                psum += __shfl_xor_sync(0xffffffffu, psum, o, 16);
            lrow[i] = lrow[i]*corr + psum;
            mrow[i] = mnew;
            #pragma unroll
            for (int j = 0; j < 4; j++) o_[i][j] *= corr;
            int qr = ty*4 + i, kc = tx*4;
            ps[qr*65 + kc+0] = p[0];
            ps[qr*65 + kc+1] = p[1];
            ps[qr*65 + kc+2] = p[2];
            ps[qr*65 + kc+3] = p[3];
        }
        __syncthreads();

        #pragma unroll 8
        for (int k = 0; k < 64; k++) {
            float4 v4 = *(const float4*)&vs[k*64 + tx*4];
            #pragma unroll
            for (int i = 0; i < 4; i++) {
                float pv = ps[(ty*4 + i)*65 + k];
                o_[i][0] += pv * v4.x;
                o_[i][1] += pv * v4.y;
                o_[i][2] += pv * v4.z;
                o_[i][3] += pv * v4.w;
            }
        }
    }

    #pragma unroll
    for (int i = 0; i < 4; i++) {
        float inv = 1.0f / lrow[i];
        int tok = b*SEQ + q0g + ty*4 + i;
        int col = h*HDIM + tx*4;
        __half2* dst = (__half2*)(outp + (size_t)tok * DIM + col);
        dst[0] = __floats2half2_rn(o_[i][0]*inv, o_[i][1]*inv);
        dst[1] = __floats2half2_rn(o_[i][2]*inv, o_[i][3]*inv);
    }
}

// ======================= host side =======================
extern "C" void kernel_launch(void* const* d_in, const int* in_sizes, int n_in,
                              void* d_out, int out_size)
{
    const float* src   = (const float*)d_in[0];
    const unsigned char* maskraw = (const unsigned char*)d_in[1];
    const float* Wqkv  = (const float*)d_in[2];
    const float* Wproj = (const float*)d_in[3];
    const float* bproj = (const float*)d_in[4];
    const float* W1    = (const float*)d_in[5];
    const float* b1    = (const float*)d_in[6];
    const float* W2    = (const float*)d_in[7];
    const float* b2    = (const float*)d_in[8];
    const float* g0    = (const float*)d_in[9];
    const float* beta0 = (const float*)d_in[10];
    const float* g1    = (const float*)d_in[11];
    const float* beta1 = (const float*)d_in[12];
    float* out = (float*)d_out;

    __half *ln, *att, *ffn, *wq, *wp, *w1c, *w2c;
    float *ln32, *x, *qkv; int* msk;
    cudaGetSymbolAddress((void**)&ln,   g_ln);
    cudaGetSymbolAddress((void**)&ln32, g_ln32);
    cudaGetSymbolAddress((void**)&qkv,  g_qkv);
    cudaGetSymbolAddress((void**)&att,  g_att);
    cudaGetSymbolAddress((void**)&x,    g_x);
    cudaGetSymbolAddress((void**)&ffn,  g_ffn);
    cudaGetSymbolAddress((void**)&msk,  g_msk);
    cudaGetSymbolAddress((void**)&wq,   g_wq);
    cudaGetSymbolAddress((void**)&wp,   g_wp);
    cudaGetSymbolAddress((void**)&w1c,  g_w1);
    cudaGetSymbolAddress((void**)&w2c,  g_w2);

    cudaFuncSetAttribute(attn_kernel, cudaFuncAttributeMaxDynamicSharedMemorySize,
                         ATTN_SMEM_BYTES);

    // 0. weights -> fp16
    cvt_h_kernel<<<(3*DIM*DIM/4 + 255)/256, 256>>>((const float4*)Wqkv,  (__half2*)wq,  3*DIM*DIM/4);
    cvt_h_kernel<<<(DIM*DIM/4   + 255)/256, 256>>>((const float4*)Wproj, (__half2*)wp,  DIM*DIM/4);
    cvt_h_kernel<<<(FDIM*DIM/4  + 255)/256, 256>>>((const float4*)W1,    (__half2*)w1c, FDIM*DIM/4);
    cvt_h_kernel<<<(DIM*FDIM/4  + 255)/256, 256>>>((const float4*)W2,    (__half2*)w2c, DIM*FDIM/4);
    // 1. normalize mask
    mask_kernel<<<1, 256>>>(maskraw, msk);
    // 2. LN0 (half out)
    ln_kernel<false><<<TOK, 256>>>(src, g0, beta0, ln, nullptr);
    // 3. QKV projection -> fp32 (feeds fp32 attention)
    gemm_mma<3*DIM, DIM, false, false, false, false>
        <<<dim3(3*DIM/128, TOK/128), 256, GSMEM_BYTES>>>(ln, wq, nullptr, nullptr, qkv);
    // 4. attention (fp32 flash, half out)
    attn_kernel<<<dim3(SEQ/64, BATCH*NHEAD), 256, ATTN_SMEM_BYTES>>>(qkv, msk, att);
    // 5. output projection + bias + residual(src) -> x (fp32)
    gemm_mma<DIM, DIM, true, false, true, false>
        <<<dim3(DIM/128, TOK/128), 256, GSMEM_BYTES>>>(att, wp, bproj, src, x);
    // 6. LN1 (half out + fp32 copy for FFN residual)
    ln_kernel<true><<<TOK, 256>>>(x, g1, beta1, ln, ln32);
    // 7. FFN1 + bias + exact GELU -> half
    gemm_mma<FDIM, DIM, true, true, false, true>
        <<<dim3(FDIM/128, TOK/128), 256, GSMEM_BYTES>>>(ln, w1c, b1, nullptr, ffn);
    // 8. FFN2 + bias + residual(LN1 fp32) -> out (fp32)
    gemm_mma<DIM, FDIM, true, false, true, false>
        <<<dim3(DIM/128, TOK/128), 256, GSMEM_BYTES>>>(ffn, w2c, b2, ln32, out);
}

// round 9
// speedup vs baseline: 1.4590x; 1.4590x over previous
#include <cuda_runtime.h>
#include <cuda_fp16.h>
#include <cfloat>
#include <math.h>
#include <stdint.h>

// Problem constants
#define BATCH 8
#define SEQ   1024
#define DIM   1024
#define NHEAD 16
#define HDIM  64
#define FDIM  4096
#define TOK   (BATCH*SEQ)   // 8192

// ---------------- scratch (static device globals; no allocation) ----------------
__device__ __half g_ln  [(size_t)TOK * DIM];    // LN out (half, feeds GEMM)
__device__ float  g_ln32[(size_t)TOK * DIM];    // LN1 fp32 copy (FFN2 residual)
__device__ float  g_qkv [(size_t)TOK * 3*DIM];  // qkv (fp32, tf32-rounded — feeds attn_mma)
__device__ __half g_att [(size_t)TOK * DIM];    // attention out (half)
__device__ float  g_x   [(size_t)TOK * DIM];    // src + proj(att) (fp32)
__device__ __half g_ffn [(size_t)TOK * FDIM];   // GELU(FFN1) (half)
__device__ int    g_msk [TOK];
// half weight copies
__device__ __half g_wq[(size_t)3*DIM*DIM];
__device__ __half g_wp[(size_t)DIM*DIM];
__device__ __half g_w1[(size_t)FDIM*DIM];
__device__ __half g_w2[(size_t)DIM*FDIM];

// ======================= small helpers =======================
__device__ __forceinline__ uint32_t smem_u32(const void* p) {
    uint32_t a;
    asm("{ .reg .u64 t; cvta.to.shared.u64 t, %1; cvt.u32.u64 %0, t; }" : "=r"(a) : "l"(p));
    return a;
}

__device__ __forceinline__ uint32_t f2tf32(float f) {
    uint32_t u;
    asm("cvt.rna.tf32.f32 %0, %1;" : "=r"(u) : "f"(f));
    return u;
}
__device__ __forceinline__ float rnd_tf32(float f) { return __uint_as_float(f2tf32(f)); }

__device__ __forceinline__ void mma_f16(float c[4],
                                        uint32_t a0, uint32_t a1, uint32_t a2, uint32_t a3,
                                        uint32_t b0, uint32_t b1) {
    asm volatile(
        "mma.sync.aligned.m16n8k16.row.col.f32.f16.f16.f32 "
        "{%0,%1,%2,%3}, {%4,%5,%6,%7}, {%8,%9}, {%0,%1,%2,%3};"
        : "+f"(c[0]), "+f"(c[1]), "+f"(c[2]), "+f"(c[3])
        : "r"(a0), "r"(a1), "r"(a2), "r"(a3), "r"(b0), "r"(b1));
}

__device__ __forceinline__ void mma_tf32(float c[4],
                                         uint32_t a0, uint32_t a1, uint32_t a2, uint32_t a3,
                                         uint32_t b0, uint32_t b1) {
    asm volatile(
        "mma.sync.aligned.m16n8k8.row.col.f32.tf32.tf32.f32 "
        "{%0,%1,%2,%3}, {%4,%5,%6,%7}, {%8,%9}, {%0,%1,%2,%3};"
        : "+f"(c[0]), "+f"(c[1]), "+f"(c[2]), "+f"(c[3])
        : "r"(a0), "r"(a1), "r"(a2), "r"(a3), "r"(b0), "r"(b1));
}

#define CP_ASYNC16(saddr, gptr) \
    asm volatile("cp.async.cg.shared.global [%0], [%1], 16;" :: "r"(saddr), "l"(gptr))
#define CP_COMMIT() asm volatile("cp.async.commit_group;")
#define CP_WAIT1()  asm volatile("cp.async.wait_group 1;")
#define CP_WAIT0()  asm volatile("cp.async.wait_group 0;")

__device__ __forceinline__ float gelu_f(float x)
{
    return 0.5f * x * (1.0f + erff(x * 0.70710678118654752f));
}

// ---------------- fp32 -> fp16 weight conversion ----------------
__global__ void cvt_h_kernel(const float4* __restrict__ in, __half2* __restrict__ out, int n4)
{
    int i = blockIdx.x * blockDim.x + threadIdx.x;
    if (i < n4) {
        float4 v = in[i];
        out[2*i]   = __floats2half2_rn(v.x, v.y);
        out[2*i+1] = __floats2half2_rn(v.z, v.w);
    }
}

// ---------------- mask dtype detection + normalization ----------------
__global__ void mask_kernel(const unsigned char* __restrict__ raw, int* __restrict__ gm)
{
    __shared__ int cnt[4];
    int t = threadIdx.x;
    if (t < 4) cnt[t] = 0;
    __syncthreads();
    int l1=0, l2=0, l3=0, lb=0;
    for (int i = t; i < TOK; i += blockDim.x) {
        unsigned char bch = raw[i];
        if (bch) {
            int m = i & 3;
            if (m == 1) l1++;
            else if (m == 2) l2++;
            else if (m == 3) l3++;
            if (bch > 1) lb++;
        }
    }
    atomicAdd(&cnt[0], l1); atomicAdd(&cnt[1], l2);
    atomicAdd(&cnt[2], l3); atomicAdd(&cnt[3], lb);
    __syncthreads();
    int c1 = cnt[0], c2 = cnt[1], c3 = cnt[2], cb = cnt[3];
    int type;
    if (c1 < 64 && c2 < 64 && c3 < 64) type = 0;
    else if (c1 < 64)                  type = 1;
    else if (cb < 64)                  type = 2;
    else                               type = 3;
    for (int i = t; i < TOK; i += blockDim.x) {
        int v;
        if      (type == 0) v = (((const int*)raw)[i] != 0);
        else if (type == 1) v = (((const float*)raw)[i] != 0.0f);
        else if (type == 2) v = (raw[i] != 0);
        else                v = (((const unsigned short*)raw)[i] != 0);
        gm[i] = v;
    }
}

// ---------------- LayerNorm: half out (+ optional fp32 copy) ----------------
template<bool WF>
__global__ void ln_kernel(const float* __restrict__ in,
                          const float* __restrict__ gamma,
                          const float* __restrict__ beta,
                          __half* __restrict__ outh,
                          float* __restrict__ outf)
{
    int row = blockIdx.x;
    int t = threadIdx.x;
    const float* xr = in + (size_t)row * DIM;
    float4 v = ((const float4*)xr)[t];
    float s = v.x + v.y + v.z + v.w;
    float q = v.x*v.x + v.y*v.y + v.z*v.z + v.w*v.w;
    #pragma unroll
    for (int o = 16; o; o >>= 1) {
        s += __shfl_xor_sync(0xffffffffu, s, o);
        q += __shfl_xor_sync(0xffffffffu, q, o);
    }
    __shared__ float ss[8], qq[8];
    if ((t & 31) == 0) { ss[t >> 5] = s; qq[t >> 5] = q; }
    __syncthreads();
    s = 0.f; q = 0.f;
    #pragma unroll
    for (int i = 0; i < 8; i++) { s += ss[i]; q += qq[i]; }
    float mean = s * (1.0f / DIM);
    float var  = q * (1.0f / DIM) - mean * mean;
    float rstd = rsqrtf(var + 1e-5f);
    float4 gv = ((const float4*)gamma)[t];
    float4 bv = ((const float4*)beta)[t];
    float ox = (v.x - mean) * rstd * gv.x + bv.x;
    float oy = (v.y - mean) * rstd * gv.y + bv.y;
    float oz = (v.z - mean) * rstd * gv.z + bv.z;
    float ow = (v.w - mean) * rstd * gv.w + bv.w;
    __half2* oh = (__half2*)(outh + (size_t)row * DIM);
    oh[2*t]   = __floats2half2_rn(ox, oy);
    oh[2*t+1] = __floats2half2_rn(oz, ow);
    if (WF) {
        float4 o = {ox, oy, oz, ow};
        ((float4*)(outf + (size_t)row * DIM))[t] = o;
    }
}

// ======================= FP16 mma.sync GEMM (proven in R8) =======================
#define SH2 20
#define HSTG (128*SH2)                    // half2 per matrix per stage (2560)
#define GSMEM_BYTES (4*HSTG*4)            // 40960

template<int N, int K, bool HAS_BIAS, bool HAS_GELU, bool HAS_RES, bool OUT_HALF, bool RND>
__global__ void __launch_bounds__(256, 2)
gemm_mma(const __half* __restrict__ A, const __half* __restrict__ Bm,
         const float* __restrict__ bias, const float* __restrict__ res,
         void* __restrict__ Cout)
{
    extern __shared__ __half2 sh[];
    __half2* As[2] = { sh,          sh + HSTG };
    __half2* Bs[2] = { sh + 2*HSTG, sh + 3*HSTG };

    int tid  = threadIdx.x;
    int lane = tid & 31, warp = tid >> 5;
    int wm = warp >> 2, wn = warp & 3;
    int gid = lane >> 2, tig = lane & 3;
    int bm = blockIdx.y * 128, bn = blockIdx.x * 128;

    int lrow = tid >> 2;          // 0..63
    int lseg = tid & 3;           // 0..3

    const __half* gA = A  + (size_t)(bm + lrow) * K + lseg * 8;
    const __half* gB = Bm + (size_t)(bn + lrow) * K + lseg * 8;

    uint32_t sA[2], sB[2];
    #pragma unroll
    for (int st = 0; st < 2; st++) {
        sA[st] = smem_u32(&As[st][lrow*SH2 + lseg*4]);
        sB[st] = smem_u32(&Bs[st][lrow*SH2 + lseg*4]);
    }
    const uint32_t SROW64 = 64u * SH2 * 4u;
    const size_t  GROW64 = (size_t)64 * K;

    int aro[4], bro[4];
    #pragma unroll
    for (int mt = 0; mt < 4; mt++) aro[mt] = (wm*64 + mt*16 + gid)*SH2 + tig;
    #pragma unroll
    for (int nt = 0; nt < 4; nt++) bro[nt] = (wn*32 + nt*8  + gid)*SH2 + tig;

    float acc[4][4][4];
    #pragma unroll
    for (int mt = 0; mt < 4; mt++)
        #pragma unroll
        for (int nt = 0; nt < 4; nt++)
            #pragma unroll
            for (int e = 0; e < 4; e++) acc[mt][nt][e] = 0.f;

    const int KT = K / 32;

    CP_ASYNC16(sA[0], gA); CP_ASYNC16(sA[0] + SROW64, gA + GROW64);
    CP_ASYNC16(sB[0], gB); CP_ASYNC16(sB[0] + SROW64, gB + GROW64);
    CP_COMMIT();

    for (int kt = 0; kt < KT; kt++) {
        int cur = kt & 1;
        if (kt + 1 < KT) {
            int nxt = cur ^ 1;
            size_t go = (size_t)(kt + 1) * 32;
            CP_ASYNC16(sA[nxt], gA + go); CP_ASYNC16(sA[nxt] + SROW64, gA + go + GROW64);
            CP_ASYNC16(sB[nxt], gB + go); CP_ASYNC16(sB[nxt] + SROW64, gB + go + GROW64);
            CP_COMMIT();
            CP_WAIT1();
        } else {
            CP_WAIT0();
        }
        __syncthreads();

        const uint32_t* a_s = (const uint32_t*)As[cur];
        const uint32_t* b_s = (const uint32_t*)Bs[cur];
        #pragma unroll
        for (int ks = 0; ks < 2; ks++) {     // 2 x k16 per BK=32
            int k0 = ks * 8;                 // half2 units
            uint32_t af[4][4];
            #pragma unroll
            for (int mt = 0; mt < 4; mt++) {
                af[mt][0] = a_s[aro[mt] + k0];
                af[mt][1] = a_s[aro[mt] + 8*SH2 + k0];
                af[mt][2] = a_s[aro[mt] + k0 + 4];
                af[mt][3] = a_s[aro[mt] + 8*SH2 + k0 + 4];
            }
            uint32_t bf[4][2];
            #pragma unroll
            for (int nt = 0; nt < 4; nt++) {
                bf[nt][0] = b_s[bro[nt] + k0];
                bf[nt][1] = b_s[bro[nt] + k0 + 4];
            }
            #pragma unroll
            for (int mt = 0; mt < 4; mt++)
                #pragma unroll
                for (int nt = 0; nt < 4; nt++)
                    mma_f16(acc[mt][nt], af[mt][0], af[mt][1], af[mt][2], af[mt][3],
                            bf[nt][0], bf[nt][1]);
        }
        __syncthreads();
    }

    #pragma unroll
    for (int mt = 0; mt < 4; mt++) {
        int row = bm + wm*64 + mt*16 + gid;
        #pragma unroll
        for (int nt = 0; nt < 4; nt++) {
            int col = bn + wn*32 + nt*8 + 2*tig;
            float2 bb = {0.f, 0.f};
            if (HAS_BIAS) bb = *(const float2*)&bias[col];
            #pragma unroll
            for (int half_ = 0; half_ < 2; half_++) {
                int rr = row + half_*8;
                float vx = acc[mt][nt][half_*2+0];
                float vy = acc[mt][nt][half_*2+1];
                if (HAS_BIAS) { vx += bb.x; vy += bb.y; }
                if (HAS_GELU) { vx = gelu_f(vx); vy = gelu_f(vy); }
                if (HAS_RES) {
                    float2 rv = *(const float2*)&res[(size_t)rr * N + col];
                    vx += rv.x; vy += rv.y;
                }
                if (OUT_HALF) {
                    __half2* cp = (__half2*)((__half*)Cout + (size_t)rr * N + col);
                    *cp = __floats2half2_rn(vx, vy);
                } else {
                    if (RND) { vx = rnd_tf32(vx); vy = rnd_tf32(vy); }
                    float2 o2 = {vx, vy};
                    *(float2*)((float*)Cout + (size_t)rr * N + col) = o2;
                }
            }
        }
    }
}

// ======================= flash attention with mma.sync tf32 (proven in R5) =======================
// block = 256 threads (8 warps), q-tile 128 (16 q-rows/warp), k-tile 64, D=64.
// SMEM (floats, stride 68 => conflict-free fragment LDS):
//   sQ[128][68] | sK[2][64][68] | sV[2][64][68] | sVT[64][68] | sP[128][68] | smk[2][64](int)
#define A_SQ   0
#define A_SK   8704
#define A_SV   17408
#define A_SVT  26112
#define A_SP   30464
#define A_SMK  39168
#define ATTN_FLOATS 39296
#define ATTN_BYTES  (ATTN_FLOATS*4)    // 157184

__global__ void __launch_bounds__(256)
attn_mma(const float* __restrict__ qkv, const int* __restrict__ gm,
         __half* __restrict__ outp)
{
    extern __shared__ float sm[];
    float* sQ  = sm + A_SQ;
    float* sK  = sm + A_SK;
    float* sV  = sm + A_SV;
    float* sVT = sm + A_SVT;
    float* sP  = sm + A_SP;
    int*   smk = (int*)(sm + A_SMK);

    const float SCALE = 0.125f;
    int tid = threadIdx.x, lane = tid & 31, warp = tid >> 5;
    int gid = lane >> 2, tig = lane & 3;
    int bh = blockIdx.y, b = bh >> 4, h = bh & 15;
    int q0 = blockIdx.x * 128;
    int qr = warp*16 + gid;           // local q row (first of pair)

    // ---- stage Q tile (128 rows x 64 floats) ----
    {
        int r = tid >> 1;
        int s0 = (tid & 1) * 8;
        const float* qp = qkv + (size_t)(b*SEQ + q0 + r) * (3*DIM) + h*HDIM;
        float* dst = sQ + r*68;
        #pragma unroll
        for (int j = 0; j < 8; j++) {
            float4 w = ((const float4*)qp)[s0 + j];
            *(float4*)&dst[(s0 + j)*4] = w;
        }
    }

    // ---- prefetch helper ----
    auto issue_tile = [&](int kt, int st) {
        int tokbase = b*SEQ + kt*64;
        int row = tid >> 4;           // 0..15
        int seg = tid & 15;           // 0..15
        const float* kg = qkv + (size_t)(tokbase + row) * (3*DIM) + DIM + h*HDIM + seg*4;
        uint32_t ka = smem_u32(&sK[st*4352 + row*68 + seg*4]);
        uint32_t va = smem_u32(&sV[st*4352 + row*68 + seg*4]);
        const size_t  GR16 = (size_t)16 * (3*DIM);
        const uint32_t SR16 = 16u * 68u * 4u;
        #pragma unroll
        for (int j = 0; j < 4; j++) {
            CP_ASYNC16(ka + j*SR16, kg + j*GR16);
            CP_ASYNC16(va + j*SR16, kg + DIM + j*GR16);
        }
        if (tid < 16) {
            uint32_t ma = smem_u32(&smk[st*64 + tid*4]);
            CP_ASYNC16(ma, gm + tokbase + tid*4);
        }
    };

    issue_tile(0, 0);
    CP_COMMIT();

    int mq0 = gm[b*SEQ + q0 + qr];
    int mq1 = gm[b*SEQ + q0 + qr + 8];

    float m0 = -FLT_MAX, m1 = -FLT_MAX, l0 = 0.f, l1 = 0.f;
    float acc[8][4];
    #pragma unroll
    for (int nt = 0; nt < 8; nt++)
        acc[nt][0] = acc[nt][1] = acc[nt][2] = acc[nt][3] = 0.f;

    const uint32_t* q_u  = (const uint32_t*)sQ;
    uint32_t*       p_u  = (uint32_t*)sP;
    const uint32_t* vt_u = (const uint32_t*)sVT;

    for (int kt = 0; kt < 16; kt++) {
        int s = kt & 1;
        CP_WAIT0();
        __syncthreads();              // tile kt data ready; all warps done with tile kt-1

        if (kt < 15) { issue_tile(kt+1, s^1); CP_COMMIT(); }

        // ---- transpose V: sV[s] -> sVT (staggered to limit bank conflicts) ----
        {
            int c4 = tid & 15, k0r = tid >> 4;
            const float* vsrc = sV + s*4352;
            #pragma unroll
            for (int j = 0; j < 4; j++) {
                int key = k0r + 16*j;
                float4 w = *(const float4*)&vsrc[key*68 + c4*4];
                float vv[4] = {w.x, w.y, w.z, w.w};
                #pragma unroll
                for (int dj = 0; dj < 4; dj++) {
                    int d2 = (dj + (c4 >> 1)) & 3;
                    sVT[(4*c4 + d2)*68 + key] = vv[d2];
                }
            }
        }
        __syncthreads();              // sVT ready

        // ---- S = Q @ K^T ----
        float sc[8][4];
        #pragma unroll
        for (int nt = 0; nt < 8; nt++)
            sc[nt][0] = sc[nt][1] = sc[nt][2] = sc[nt][3] = 0.f;
        {
            const uint32_t* k_u = (const uint32_t*)(sK + s*4352);
            #pragma unroll
            for (int ks = 0; ks < 8; ks++) {
                int k0 = 8*ks;
                uint32_t a0 = q_u[qr*68 + tig + k0];
                uint32_t a1 = q_u[(qr+8)*68 + tig + k0];
                uint32_t a2 = q_u[qr*68 + tig + 4 + k0];
                uint32_t a3 = q_u[(qr+8)*68 + tig + 4 + k0];
                #pragma unroll
                for (int nt = 0; nt < 8; nt++) {
                    uint32_t b0 = k_u[(8*nt+gid)*68 + tig + k0];
                    uint32_t b1 = k_u[(8*nt+gid)*68 + tig + 4 + k0];
                    mma_tf32(sc[nt], a0, a1, a2, a3, b0, b1);
                }
            }
        }

        // ---- mask + online softmax (row stats over 4-lane tig group) ----
        float mx0 = -FLT_MAX, mx1 = -FLT_MAX;
        #pragma unroll
        for (int nt = 0; nt < 8; nt++) {
            int kk = 8*nt + 2*tig;
            int ka_ = smk[s*64 + kk], kb_ = smk[s*64 + kk + 1];
            sc[nt][0] = (mq0 && ka_) ? sc[nt][0]*SCALE : -FLT_MAX;
            sc[nt][1] = (mq0 && kb_) ? sc[nt][1]*SCALE : -FLT_MAX;
            sc[nt][2] = (mq1 && ka_) ? sc[nt][2]*SCALE : -FLT_MAX;
            sc[nt][3] = (mq1 && kb_) ? sc[nt][3]*SCALE : -FLT_MAX;
            mx0 = fmaxf(mx0, fmaxf(sc[nt][0], sc[nt][1]));
            mx1 = fmaxf(mx1, fmaxf(sc[nt][2], sc[nt][3]));
        }
        mx0 = fmaxf(mx0, __shfl_xor_sync(0xffffffffu, mx0, 1));
        mx0 = fmaxf(mx0, __shfl_xor_sync(0xffffffffu, mx0, 2));
        mx1 = fmaxf(mx1, __shfl_xor_sync(0xffffffffu, mx1, 1));
        mx1 = fmaxf(mx1, __shfl_xor_sync(0xffffffffu, mx1, 2));

        float mn0 = fmaxf(m0, mx0), mn1 = fmaxf(m1, mx1);
        float c0 = __expf(m0 - mn0), c1 = __expf(m1 - mn1);
        float ps0 = 0.f, ps1 = 0.f;
        #pragma unroll
        for (int nt = 0; nt < 8; nt++) {
            float p00 = __expf(sc[nt][0] - mn0);
            float p01 = __expf(sc[nt][1] - mn0);
            float p10 = __expf(sc[nt][2] - mn1);
            float p11 = __expf(sc[nt][3] - mn1);
            ps0 += p00 + p01; ps1 += p10 + p11;
            int col = 8*nt + 2*tig;
            p_u[qr*68 + col]       = f2tf32(p00);
            p_u[qr*68 + col + 1]   = f2tf32(p01);
            p_u[(qr+8)*68 + col]     = f2tf32(p10);
            p_u[(qr+8)*68 + col + 1] = f2tf32(p11);
        }
        ps0 += __shfl_xor_sync(0xffffffffu, ps0, 1);
        ps0 += __shfl_xor_sync(0xffffffffu, ps0, 2);
        ps1 += __shfl_xor_sync(0xffffffffu, ps1, 1);
        ps1 += __shfl_xor_sync(0xffffffffu, ps1, 2);
        l0 = l0*c0 + ps0; l1 = l1*c1 + ps1;
        m0 = mn0; m1 = mn1;
        #pragma unroll
        for (int nt = 0; nt < 8; nt++) {
            acc[nt][0] *= c0; acc[nt][1] *= c0;
            acc[nt][2] *= c1; acc[nt][3] *= c1;
        }
        __syncwarp();                 // P is warp-private: STS -> LDS visibility

        // ---- O += P @ V ----
        #pragma unroll
        for (int ks = 0; ks < 8; ks++) {
            int k0 = 8*ks;
            uint32_t a0 = p_u[qr*68 + tig + k0];
            uint32_t a1 = p_u[(qr+8)*68 + tig + k0];
            uint32_t a2 = p_u[qr*68 + tig + 4 + k0];
            uint32_t a3 = p_u[(qr+8)*68 + tig + 4 + k0];
            #pragma unroll
            for (int nt = 0; nt < 8; nt++) {
                uint32_t b0 = vt_u[(8*nt+gid)*68 + tig + k0];
                uint32_t b1 = vt_u[(8*nt+gid)*68 + tig + 4 + k0];
                mma_tf32(acc[nt], a0, a1, a2, a3, b0, b1);
            }
        }
    }

    // ---- epilogue: /l, store half (feeds fp16 proj GEMM) ----
    float inv0 = 1.0f / l0, inv1 = 1.0f / l1;
    __half* op0 = outp + (size_t)(b*SEQ + q0 + qr) * DIM + h*HDIM;
    __half* op1 = outp + (size_t)(b*SEQ + q0 + qr + 8) * DIM + h*HDIM;
    #pragma unroll
    for (int nt = 0; nt < 8; nt++) {
        int col = 8*nt + 2*tig;
        *(__half2*)&op0[col] = __floats2half2_rn(acc[nt][0]*inv0, acc[nt][1]*inv0);
        *(__half2*)&op1[col] = __floats2half2_rn(acc[nt][2]*inv1, acc[nt][3]*inv1);
    }
}

// ======================= host side =======================
extern "C" void kernel_launch(void* const* d_in, const int* in_sizes, int n_in,
                              void* d_out, int out_size)
{
    const float* src   = (const float*)d_in[0];
    const unsigned char* maskraw = (const unsigned char*)d_in[1];
    const float* Wqkv  = (const float*)d_in[2];
    const float* Wproj = (const float*)d_in[3];
    const float* bproj = (const float*)d_in[4];
    const float* W1    = (const float*)d_in[5];
    const float* b1    = (const float*)d_in[6];
    const float* W2    = (const float*)d_in[7];
    const float* b2    = (const float*)d_in[8];
    const float* g0    = (const float*)d_in[9];
    const float* beta0 = (const float*)d_in[10];
    const float* g1    = (const float*)d_in[11];
    const float* beta1 = (const float*)d_in[12];
    float* out = (float*)d_out;

    __half *ln, *att, *ffn, *wq, *wp, *w1c, *w2c;
    float *ln32, *x, *qkv; int* msk;
    cudaGetSymbolAddress((void**)&ln,   g_ln);
    cudaGetSymbolAddress((void**)&ln32, g_ln32);
    cudaGetSymbolAddress((void**)&qkv,  g_qkv);
    cudaGetSymbolAddress((void**)&att,  g_att);
    cudaGetSymbolAddress((void**)&x,    g_x);
    cudaGetSymbolAddress((void**)&ffn,  g_ffn);
    cudaGetSymbolAddress((void**)&msk,  g_msk);
    cudaGetSymbolAddress((void**)&wq,   g_wq);
    cudaGetSymbolAddress((void**)&wp,   g_wp);
    cudaGetSymbolAddress((void**)&w1c,  g_w1);
    cudaGetSymbolAddress((void**)&w2c,  g_w2);

    cudaFuncSetAttribute(attn_mma, cudaFuncAttributeMaxDynamicSharedMemorySize, ATTN_BYTES);

    // 0. weights -> fp16
    cvt_h_kernel<<<(3*DIM*DIM/4 + 255)/256, 256>>>((const float4*)Wqkv,  (__half2*)wq,  3*DIM*DIM/4);
    cvt_h_kernel<<<(DIM*DIM/4   + 255)/256, 256>>>((const float4*)Wproj, (__half2*)wp,  DIM*DIM/4);
    cvt_h_kernel<<<(FDIM*DIM/4  + 255)/256, 256>>>((const float4*)W1,    (__half2*)w1c, FDIM*DIM/4);
    cvt_h_kernel<<<(DIM*FDIM/4  + 255)/256, 256>>>((const float4*)W2,    (__half2*)w2c, DIM*FDIM/4);
    // 1. normalize mask
    mask_kernel<<<1, 256>>>(maskraw, msk);
    // 2. LN0 (half out)
    ln_kernel<false><<<TOK, 256>>>(src, g0, beta0, ln, nullptr);
    // 3. QKV projection -> fp32 tf32-rounded (feeds tf32 attn_mma)
    gemm_mma<3*DIM, DIM, false, false, false, false, true>
        <<<dim3(3*DIM/128, TOK/128), 256, GSMEM_BYTES>>>(ln, wq, nullptr, nullptr, qkv);
    // 4. attention (tf32 tensor-core flash, half out)
    attn_mma<<<dim3(SEQ/128, BATCH*NHEAD), 256, ATTN_BYTES>>>(qkv, msk, att);
    // 5. output projection + bias + residual(src) -> x (fp32)
    gemm_mma<DIM, DIM, true, false, true, false, false>
        <<<dim3(DIM/128, TOK/128), 256, GSMEM_BYTES>>>(att, wp, bproj, src, x);
    // 6. LN1 (half out + fp32 copy for FFN residual)
    ln_kernel<true><<<TOK, 256>>>(x, g1, beta1, ln, ln32);
    // 7. FFN1 + bias + exact GELU -> half
    gemm_mma<FDIM, DIM, true, true, false, true, false>
        <<<dim3(FDIM/128, TOK/128), 256, GSMEM_BYTES>>>(ln, w1c, b1, nullptr, ffn);
    // 8. FFN2 + bias + residual(LN1 fp32) -> out (fp32)
    gemm_mma<DIM, FDIM, true, false, true, false, false>
        <<<dim3(DIM/128, TOK/128), 256, GSMEM_BYTES>>>(ffn, w2c, b2, ln32, out);
}

// round 10
// speedup vs baseline: 1.8171x; 1.2454x over previous
#include <cuda_runtime.h>
#include <cuda_fp16.h>
#include <cfloat>
#include <math.h>
#include <stdint.h>

// Problem constants
#define BATCH 8
#define SEQ   1024
#define DIM   1024
#define NHEAD 16
#define HDIM  64
#define FDIM  4096
#define TOK   (BATCH*SEQ)   // 8192

// ---------------- scratch (static device globals; no allocation) ----------------
__device__ __half g_ln  [(size_t)TOK * DIM];    // LN out (half, feeds GEMM)
__device__ float  g_ln32[(size_t)TOK * DIM];    // LN1 fp32 copy (FFN2 residual)
__device__ float  g_qkv [(size_t)TOK * 3*DIM];  // qkv (fp32, tf32-rounded — feeds attn_mma)
__device__ __half g_att [(size_t)TOK * DIM];    // attention out (half)
__device__ float  g_x   [(size_t)TOK * DIM];    // src + proj(att) (fp32)
__device__ __half g_ffn [(size_t)TOK * FDIM];   // GELU(FFN1) (half)
__device__ int    g_msk [TOK];
// half weight copies
__device__ __half g_wq[(size_t)3*DIM*DIM];
__device__ __half g_wp[(size_t)DIM*DIM];
__device__ __half g_w1[(size_t)FDIM*DIM];
__device__ __half g_w2[(size_t)DIM*FDIM];

// ======================= small helpers =======================
__device__ __forceinline__ uint32_t smem_u32(const void* p) {
    uint32_t a;
    asm("{ .reg .u64 t; cvta.to.shared.u64 t, %1; cvt.u32.u64 %0, t; }" : "=r"(a) : "l"(p));
    return a;
}

__device__ __forceinline__ uint32_t f2tf32(float f) {
    uint32_t u;
    asm("cvt.rna.tf32.f32 %0, %1;" : "=r"(u) : "f"(f));
    return u;
}
__device__ __forceinline__ float rnd_tf32(float f) { return __uint_as_float(f2tf32(f)); }

__device__ __forceinline__ void mma_f16(float c[4],
                                        uint32_t a0, uint32_t a1, uint32_t a2, uint32_t a3,
                                        uint32_t b0, uint32_t b1) {
    asm volatile(
        "mma.sync.aligned.m16n8k16.row.col.f32.f16.f16.f32 "
        "{%0,%1,%2,%3}, {%4,%5,%6,%7}, {%8,%9}, {%0,%1,%2,%3};"
        : "+f"(c[0]), "+f"(c[1]), "+f"(c[2]), "+f"(c[3])
        : "r"(a0), "r"(a1), "r"(a2), "r"(a3), "r"(b0), "r"(b1));
}

__device__ __forceinline__ void mma_tf32(float c[4],
                                         uint32_t a0, uint32_t a1, uint32_t a2, uint32_t a3,
                                         uint32_t b0, uint32_t b1) {
    asm volatile(
        "mma.sync.aligned.m16n8k8.row.col.f32.tf32.tf32.f32 "
        "{%0,%1,%2,%3}, {%4,%5,%6,%7}, {%8,%9}, {%0,%1,%2,%3};"
        : "+f"(c[0]), "+f"(c[1]), "+f"(c[2]), "+f"(c[3])
        : "r"(a0), "r"(a1), "r"(a2), "r"(a3), "r"(b0), "r"(b1));
}

#define LDSM_X4(r0, r1, r2, r3, addr) \
    asm volatile("ldmatrix.sync.aligned.m8n8.x4.shared.b16 {%0,%1,%2,%3}, [%4];" \
        : "=r"(r0), "=r"(r1), "=r"(r2), "=r"(r3) : "r"(addr))

#define CP_ASYNC16(saddr, gptr) \
    asm volatile("cp.async.cg.shared.global [%0], [%1], 16;" :: "r"(saddr), "l"(gptr))
#define CP_COMMIT() asm volatile("cp.async.commit_group;")
#define CP_WAIT1()  asm volatile("cp.async.wait_group 1;")
#define CP_WAIT0()  asm volatile("cp.async.wait_group 0;")

__device__ __forceinline__ float gelu_f(float x)
{
    return 0.5f * x * (1.0f + erff(x * 0.70710678118654752f));
}

// ---------------- fp32 -> fp16 weight conversion ----------------
__global__ void cvt_h_kernel(const float4* __restrict__ in, __half2* __restrict__ out, int n4)
{
    int i = blockIdx.x * blockDim.x + threadIdx.x;
    if (i < n4) {
        float4 v = in[i];
        out[2*i]   = __floats2half2_rn(v.x, v.y);
        out[2*i+1] = __floats2half2_rn(v.z, v.w);
    }
}

// ---------------- mask dtype detection + normalization ----------------
__global__ void mask_kernel(const unsigned char* __restrict__ raw, int* __restrict__ gm)
{
    __shared__ int cnt[4];
    int t = threadIdx.x;
    if (t < 4) cnt[t] = 0;
    __syncthreads();
    int l1=0, l2=0, l3=0, lb=0;
    for (int i = t; i < TOK; i += blockDim.x) {
        unsigned char bch = raw[i];
        if (bch) {
            int m = i & 3;
            if (m == 1) l1++;
            else if (m == 2) l2++;
            else if (m == 3) l3++;
            if (bch > 1) lb++;
        }
    }
    atomicAdd(&cnt[0], l1); atomicAdd(&cnt[1], l2);
    atomicAdd(&cnt[2], l3); atomicAdd(&cnt[3], lb);
    __syncthreads();
    int c1 = cnt[0], c2 = cnt[1], c3 = cnt[2], cb = cnt[3];
    int type;
    if (c1 < 64 && c2 < 64 && c3 < 64) type = 0;
    else if (c1 < 64)                  type = 1;
    else if (cb < 64)                  type = 2;
    else                               type = 3;
    for (int i = t; i < TOK; i += blockDim.x) {
        int v;
        if      (type == 0) v = (((const int*)raw)[i] != 0);
        else if (type == 1) v = (((const float*)raw)[i] != 0.0f);
        else if (type == 2) v = (raw[i] != 0);
        else                v = (((const unsigned short*)raw)[i] != 0);
        gm[i] = v;
    }
}

// ---------------- LayerNorm: half out (+ optional fp32 copy) ----------------
template<bool WF>
__global__ void ln_kernel(const float* __restrict__ in,
                          const float* __restrict__ gamma,
                          const float* __restrict__ beta,
                          __half* __restrict__ outh,
                          float* __restrict__ outf)
{
    int row = blockIdx.x;
    int t = threadIdx.x;
    const float* xr = in + (size_t)row * DIM;
    float4 v = ((const float4*)xr)[t];
    float s = v.x + v.y + v.z + v.w;
    float q = v.x*v.x + v.y*v.y + v.z*v.z + v.w*v.w;
    #pragma unroll
    for (int o = 16; o; o >>= 1) {
        s += __shfl_xor_sync(0xffffffffu, s, o);
        q += __shfl_xor_sync(0xffffffffu, q, o);
    }
    __shared__ float ss[8], qq[8];
    if ((t & 31) == 0) { ss[t >> 5] = s; qq[t >> 5] = q; }
    __syncthreads();
    s = 0.f; q = 0.f;
    #pragma unroll
    for (int i = 0; i < 8; i++) { s += ss[i]; q += qq[i]; }
    float mean = s * (1.0f / DIM);
    float var  = q * (1.0f / DIM) - mean * mean;
    float rstd = rsqrtf(var + 1e-5f);
    float4 gv = ((const float4*)gamma)[t];
    float4 bv = ((const float4*)beta)[t];
    float ox = (v.x - mean) * rstd * gv.x + bv.x;
    float oy = (v.y - mean) * rstd * gv.y + bv.y;
    float oz = (v.z - mean) * rstd * gv.z + bv.z;
    float ow = (v.w - mean) * rstd * gv.w + bv.w;
    __half2* oh = (__half2*)(outh + (size_t)row * DIM);
    oh[2*t]   = __floats2half2_rn(ox, oy);
    oh[2*t+1] = __floats2half2_rn(oz, ow);
    if (WF) {
        float4 o = {ox, oy, oz, ow};
        ((float4*)(outf + (size_t)row * DIM))[t] = o;
    }
}

// ======================= FP16 mma.sync GEMM (ldmatrix fragments) =======================
// C[M,N] = A[M,K] @ B[N,K]^T (+bias/gelu/res). 128x128x32 tile, 8 warps (2m x 4n),
// warp tile 64x32, m16n8k16. Row stride 20 half2 (80B) -> LDSM conflict-free.
#define SH2 20
#define HSTG (128*SH2)                    // half2 per matrix per stage (2560)
#define HSTG_B (HSTG*4)                   // stage stride in bytes (10240)
#define GSMEM_BYTES (4*HSTG*4)            // 40960

template<int N, int K, bool HAS_BIAS, bool HAS_GELU, bool HAS_RES, bool OUT_HALF, bool RND>
__global__ void __launch_bounds__(256, 2)
gemm_mma(const __half* __restrict__ A, const __half* __restrict__ Bm,
         const float* __restrict__ bias, const float* __restrict__ res,
         void* __restrict__ Cout)
{
    extern __shared__ __half2 sh[];
    __half2* As0 = sh;               // stage stride HSTG
    __half2* Bs0 = sh + 2*HSTG;

    int tid  = threadIdx.x;
    int lane = tid & 31, warp = tid >> 5;
    int wm = warp >> 2, wn = warp & 3;
    int gid = lane >> 2, tig = lane & 3;
    int bm = blockIdx.y * 128, bn = blockIdx.x * 128;

    // ---- cp.async loader mapping (proven) ----
    int lrow = tid >> 2;          // 0..63
    int lseg = tid & 3;           // 0..3
    const __half* gA = A  + (size_t)(bm + lrow) * K + lseg * 8;
    const __half* gB = Bm + (size_t)(bn + lrow) * K + lseg * 8;
    uint32_t sA[2], sB[2];
    #pragma unroll
    for (int st = 0; st < 2; st++) {
        sA[st] = smem_u32(&As0[st*HSTG + lrow*SH2 + lseg*4]);
        sB[st] = smem_u32(&Bs0[st*HSTG + lrow*SH2 + lseg*4]);
    }
    const uint32_t SROW64 = 64u * SH2 * 4u;
    const size_t  GROW64 = (size_t)64 * K;

    // ---- ldmatrix per-lane addresses (stage 0; stage 1 = +HSTG_B) ----
    // A: per mt, x4 = (rows0-7,k0)(rows8-15,k0)(rows0-7,k8)(rows8-15,k8)
    int lane15 = lane & 15;
    int lq     = lane >> 4;       // 0/1 -> k0/k8 halves (+16B)
    uint32_t aAddr[4];
    #pragma unroll
    for (int mt = 0; mt < 4; mt++)
        aAddr[mt] = smem_u32(&As0[(wm*64 + mt*16 + lane15)*SH2]) + lq*16;
    // B: per nt-pair p, x4 = (nt,k0)(nt,k8)(nt+1,k0)(nt+1,k8)
    uint32_t bAddr[2];
    {
        int quad = lane >> 3;     // 0..3
        int l7   = lane & 7;
        #pragma unroll
        for (int p = 0; p < 2; p++) {
            int row = wn*32 + (2*p + (quad >> 1))*8 + l7;
            bAddr[p] = smem_u32(&Bs0[row*SH2]) + (quad & 1)*16;
        }
    }

    float acc[4][4][4];
    #pragma unroll
    for (int mt = 0; mt < 4; mt++)
        #pragma unroll
        for (int nt = 0; nt < 4; nt++)
            #pragma unroll
            for (int e = 0; e < 4; e++) acc[mt][nt][e] = 0.f;

    const int KT = K / 32;

    CP_ASYNC16(sA[0], gA); CP_ASYNC16(sA[0] + SROW64, gA + GROW64);
    CP_ASYNC16(sB[0], gB); CP_ASYNC16(sB[0] + SROW64, gB + GROW64);
    CP_COMMIT();

    for (int kt = 0; kt < KT; kt++) {
        int cur = kt & 1;
        if (kt + 1 < KT) {
            int nxt = cur ^ 1;
            size_t go = (size_t)(kt + 1) * 32;
            CP_ASYNC16(sA[nxt], gA + go); CP_ASYNC16(sA[nxt] + SROW64, gA + go + GROW64);
            CP_ASYNC16(sB[nxt], gB + go); CP_ASYNC16(sB[nxt] + SROW64, gB + go + GROW64);
            CP_COMMIT();
            CP_WAIT1();
        } else {
            CP_WAIT0();
        }
        __syncthreads();

        uint32_t stoff = (uint32_t)cur * HSTG_B;
        #pragma unroll
        for (int ks = 0; ks < 2; ks++) {     // 2 x k16 per BK=32
            uint32_t ko = ks * 32;           // bytes
            uint32_t af[4][4];
            #pragma unroll
            for (int mt = 0; mt < 4; mt++)
                LDSM_X4(af[mt][0], af[mt][1], af[mt][2], af[mt][3],
                        aAddr[mt] + stoff + ko);
            uint32_t bf[4][2];
            #pragma unroll
            for (int p = 0; p < 2; p++)
                LDSM_X4(bf[2*p][0], bf[2*p][1], bf[2*p+1][0], bf[2*p+1][1],
                        bAddr[p] + stoff + ko);
            #pragma unroll
            for (int mt = 0; mt < 4; mt++)
                #pragma unroll
                for (int nt = 0; nt < 4; nt++)
                    mma_f16(acc[mt][nt], af[mt][0], af[mt][1], af[mt][2], af[mt][3],
                            bf[nt][0], bf[nt][1]);
        }
        __syncthreads();
    }

    #pragma unroll
    for (int mt = 0; mt < 4; mt++) {
        int row = bm + wm*64 + mt*16 + gid;
        #pragma unroll
        for (int nt = 0; nt < 4; nt++) {
            int col = bn + wn*32 + nt*8 + 2*tig;
            float2 bb = {0.f, 0.f};
            if (HAS_BIAS) bb = *(const float2*)&bias[col];
            #pragma unroll
            for (int half_ = 0; half_ < 2; half_++) {
                int rr = row + half_*8;
                float vx = acc[mt][nt][half_*2+0];
                float vy = acc[mt][nt][half_*2+1];
                if (HAS_BIAS) { vx += bb.x; vy += bb.y; }
                if (HAS_GELU) { vx = gelu_f(vx); vy = gelu_f(vy); }
                if (HAS_RES) {
                    float2 rv = *(const float2*)&res[(size_t)rr * N + col];
                    vx += rv.x; vy += rv.y;
                }
                if (OUT_HALF) {
                    __half2* cp = (__half2*)((__half*)Cout + (size_t)rr * N + col);
                    *cp = __floats2half2_rn(vx, vy);
                } else {
                    if (RND) { vx = rnd_tf32(vx); vy = rnd_tf32(vy); }
                    float2 o2 = {vx, vy};
                    *(float2*)((float*)Cout + (size_t)rr * N + col) = o2;
                }
            }
        }
    }
}

// ======================= flash attention with mma.sync tf32 (proven in R5/R9) =======================
#define A_SQ   0
#define A_SK   8704
#define A_SV   17408
#define A_SVT  26112
#define A_SP   30464
#define A_SMK  39168
#define ATTN_FLOATS 39296
#define ATTN_BYTES  (ATTN_FLOATS*4)    // 157184

__global__ void __launch_bounds__(256)
attn_mma(const float* __restrict__ qkv, const int* __restrict__ gm,
         __half* __restrict__ outp)
{
    extern __shared__ float sm[];
    float* sQ  = sm + A_SQ;
    float* sK  = sm + A_SK;
    float* sV  = sm + A_SV;
    float* sVT = sm + A_SVT;
    float* sP  = sm + A_SP;
    int*   smk = (int*)(sm + A_SMK);

    const float SCALE = 0.125f;
    int tid = threadIdx.x, lane = tid & 31, warp = tid >> 5;
    int gid = lane >> 2, tig = lane & 3;
    int bh = blockIdx.y, b = bh >> 4, h = bh & 15;
    int q0 = blockIdx.x * 128;
    int qr = warp*16 + gid;

    {
        int r = tid >> 1;
        int s0 = (tid & 1) * 8;
        const float* qp = qkv + (size_t)(b*SEQ + q0 + r) * (3*DIM) + h*HDIM;
        float* dst = sQ + r*68;
        #pragma unroll
        for (int j = 0; j < 8; j++) {
            float4 w = ((const float4*)qp)[s0 + j];
            *(float4*)&dst[(s0 + j)*4] = w;
        }
    }

    auto issue_tile = [&](int kt, int st) {
        int tokbase = b*SEQ + kt*64;
        int row = tid >> 4;
        int seg = tid & 15;
        const float* kg = qkv + (size_t)(tokbase + row) * (3*DIM) + DIM + h*HDIM + seg*4;
        uint32_t ka = smem_u32(&sK[st*4352 + row*68 + seg*4]);
        uint32_t va = smem_u32(&sV[st*4352 + row*68 + seg*4]);
        const size_t  GR16 = (size_t)16 * (3*DIM);
        const uint32_t SR16 = 16u * 68u * 4u;
        #pragma unroll
        for (int j = 0; j < 4; j++) {
            CP_ASYNC16(ka + j*SR16, kg + j*GR16);
            CP_ASYNC16(va + j*SR16, kg + DIM + j*GR16);
        }
        if (tid < 16) {
            uint32_t ma = smem_u32(&smk[st*64 + tid*4]);
            CP_ASYNC16(ma, gm + tokbase + tid*4);
        }
    };

    issue_tile(0, 0);
    CP_COMMIT();

    int mq0 = gm[b*SEQ + q0 + qr];
    int mq1 = gm[b*SEQ + q0 + qr + 8];

    float m0 = -FLT_MAX, m1 = -FLT_MAX, l0 = 0.f, l1 = 0.f;
    float acc[8][4];
    #pragma unroll
    for (int nt = 0; nt < 8; nt++)
        acc[nt][0] = acc[nt][1] = acc[nt][2] = acc[nt][3] = 0.f;

    const uint32_t* q_u  = (const uint32_t*)sQ;
    uint32_t*       p_u  = (uint32_t*)sP;
    const uint32_t* vt_u = (const uint32_t*)sVT;

    for (int kt = 0; kt < 16; kt++) {
        int s = kt & 1;
        CP_WAIT0();
        __syncthreads();

        if (kt < 15) { issue_tile(kt+1, s^1); CP_COMMIT(); }

        {
            int c4 = tid & 15, k0r = tid >> 4;
            const float* vsrc = sV + s*4352;
            #pragma unroll
            for (int j = 0; j < 4; j++) {
                int key = k0r + 16*j;
                float4 w = *(const float4*)&vsrc[key*68 + c4*4];
                float vv[4] = {w.x, w.y, w.z, w.w};
                #pragma unroll
                for (int dj = 0; dj < 4; dj++) {
                    int d2 = (dj + (c4 >> 1)) & 3;
                    sVT[(4*c4 + d2)*68 + key] = vv[d2];
                }
            }
        }
        __syncthreads();

        float sc[8][4];
        #pragma unroll
        for (int nt = 0; nt < 8; nt++)
            sc[nt][0] = sc[nt][1] = sc[nt][2] = sc[nt][3] = 0.f;
        {
            const uint32_t* k_u = (const uint32_t*)(sK + s*4352);
            #pragma unroll
            for (int ks = 0; ks < 8; ks++) {
                int k0 = 8*ks;
                uint32_t a0 = q_u[qr*68 + tig + k0];
                uint32_t a1 = q_u[(qr+8)*68 + tig + k0];
                uint32_t a2 = q_u[qr*68 + tig + 4 + k0];
                uint32_t a3 = q_u[(qr+8)*68 + tig + 4 + k0];
                #pragma unroll
                for (int nt = 0; nt < 8; nt++) {
                    uint32_t b0 = k_u[(8*nt+gid)*68 + tig + k0];
                    uint32_t b1 = k_u[(8*nt+gid)*68 + tig + 4 + k0];
                    mma_tf32(sc[nt], a0, a1, a2, a3, b0, b1);
                }
            }
        }

        float mx0 = -FLT_MAX, mx1 = -FLT_MAX;
        #pragma unroll
        for (int nt = 0; nt < 8; nt++) {
            int kk = 8*nt + 2*tig;
            int ka_ = smk[s*64 + kk], kb_ = smk[s*64 + kk + 1];
            sc[nt][0] = (mq0 && ka_) ? sc[nt][0]*SCALE : -FLT_MAX;
            sc[nt][1] = (mq0 && kb_) ? sc[nt][1]*SCALE : -FLT_MAX;
            sc[nt][2] = (mq1 && ka_) ? sc[nt][2]*SCALE : -FLT_MAX;
            sc[nt][3] = (mq1 && kb_) ? sc[nt][3]*SCALE : -FLT_MAX;
            mx0 = fmaxf(mx0, fmaxf(sc[nt][0], sc[nt][1]));
            mx1 = fmaxf(mx1, fmaxf(sc[nt][2], sc[nt][3]));
        }
        mx0 = fmaxf(mx0, __shfl_xor_sync(0xffffffffu, mx0, 1));
        mx0 = fmaxf(mx0, __shfl_xor_sync(0xffffffffu, mx0, 2));
        mx1 = fmaxf(mx1, __shfl_xor_sync(0xffffffffu, mx1, 1));
        mx1 = fmaxf(mx1, __shfl_xor_sync(0xffffffffu, mx1, 2));

        float mn0 = fmaxf(m0, mx0), mn1 = fmaxf(m1, mx1);
        float c0 = __expf(m0 - mn0), c1 = __expf(m1 - mn1);
        float ps0 = 0.f, ps1 = 0.f;
        #pragma unroll
        for (int nt = 0; nt < 8; nt++) {
            float p00 = __expf(sc[nt][0] - mn0);
            float p01 = __expf(sc[nt][1] - mn0);
            float p10 = __expf(sc[nt][2] - mn1);
            float p11 = __expf(sc[nt][3] - mn1);
            ps0 += p00 + p01; ps1 += p10 + p11;
            int col = 8*nt + 2*tig;
            p_u[qr*68 + col]       = f2tf32(p00);
            p_u[qr*68 + col + 1]   = f2tf32(p01);
            p_u[(qr+8)*68 + col]     = f2tf32(p10);
            p_u[(qr+8)*68 + col + 1] = f2tf32(p11);
        }
        ps0 += __shfl_xor_sync(0xffffffffu, ps0, 1);
        ps0 += __shfl_xor_sync(0xffffffffu, ps0, 2);
        ps1 += __shfl_xor_sync(0xffffffffu, ps1, 1);
        ps1 += __shfl_xor_sync(0xffffffffu, ps1, 2);
        l0 = l0*c0 + ps0; l1 = l1*c1 + ps1;
        m0 = mn0; m1 = mn1;
        #pragma unroll
        for (int nt = 0; nt < 8; nt++) {
            acc[nt][0] *= c0; acc[nt][1] *= c0;
            acc[nt][2] *= c1; acc[nt][3] *= c1;
        }
        __syncwarp();

        #pragma unroll
        for (int ks = 0; ks < 8; ks++) {
            int k0 = 8*ks;
            uint32_t a0 = p_u[qr*68 + tig + k0];
            uint32_t a1 = p_u[(qr+8)*68 + tig + k0];
            uint32_t a2 = p_u[qr*68 + tig + 4 + k0];
            uint32_t a3 = p_u[(qr+8)*68 + tig + 4 + k0];
            #pragma unroll
            for (int nt = 0; nt < 8; nt++) {
                uint32_t b0 = vt_u[(8*nt+gid)*68 + tig + k0];
                uint32_t b1 = vt_u[(8*nt+gid)*68 + tig + 4 + k0];
                mma_tf32(acc[nt], a0, a1, a2, a3, b0, b1);
            }
        }
    }

    float inv0 = 1.0f / l0, inv1 = 1.0f / l1;
    __half* op0 = outp + (size_t)(b*SEQ + q0 + qr) * DIM + h*HDIM;
    __half* op1 = outp + (size_t)(b*SEQ + q0 + qr + 8) * DIM + h*HDIM;
    #pragma unroll
    for (int nt = 0; nt < 8; nt++) {
        int col = 8*nt + 2*tig;
        *(__half2*)&op0[col] = __floats2half2_rn(acc[nt][0]*inv0, acc[nt][1]*inv0);
        *(__half2*)&op1[col] = __floats2half2_rn(acc[nt][2]*inv1, acc[nt][3]*inv1);
    }
}

// ======================= host side =======================
extern "C" void kernel_launch(void* const* d_in, const int* in_sizes, int n_in,
                              void* d_out, int out_size)
{
    const float* src   = (const float*)d_in[0];
    const unsigned char* maskraw = (const unsigned char*)d_in[1];
    const float* Wqkv  = (const float*)d_in[2];
    const float* Wproj = (const float*)d_in[3];
    const float* bproj = (const float*)d_in[4];
    const float* W1    = (const float*)d_in[5];
    const float* b1    = (const float*)d_in[6];
    const float* W2    = (const float*)d_in[7];
    const float* b2    = (const float*)d_in[8];
    const float* g0    = (const float*)d_in[9];
    const float* beta0 = (const float*)d_in[10];
    const float* g1    = (const float*)d_in[11];
    const float* beta1 = (const float*)d_in[12];
    float* out = (float*)d_out;

    __half *ln, *att, *ffn, *wq, *wp, *w1c, *w2c;
    float *ln32, *x, *qkv; int* msk;
    cudaGetSymbolAddress((void**)&ln,   g_ln);
    cudaGetSymbolAddress((void**)&ln32, g_ln32);
    cudaGetSymbolAddress((void**)&qkv,  g_qkv);
    cudaGetSymbolAddress((void**)&att,  g_att);
    cudaGetSymbolAddress((void**)&x,    g_x);
    cudaGetSymbolAddress((void**)&ffn,  g_ffn);
    cudaGetSymbolAddress((void**)&msk,  g_msk);
    cudaGetSymbolAddress((void**)&wq,   g_wq);
    cudaGetSymbolAddress((void**)&wp,   g_wp);
    cudaGetSymbolAddress((void**)&w1c,  g_w1);
    cudaGetSymbolAddress((void**)&w2c,  g_w2);

    cudaFuncSetAttribute(attn_mma, cudaFuncAttributeMaxDynamicSharedMemorySize, ATTN_BYTES);

    // 0. weights -> fp16
    cvt_h_kernel<<<(3*DIM*DIM/4 + 255)/256, 256>>>((const float4*)Wqkv,  (__half2*)wq,  3*DIM*DIM/4);
    cvt_h_kernel<<<(DIM*DIM/4   + 255)/256, 256>>>((const float4*)Wproj, (__half2*)wp,  DIM*DIM/4);
    cvt_h_kernel<<<(FDIM*DIM/4  + 255)/256, 256>>>((const float4*)W1,    (__half2*)w1c, FDIM*DIM/4);
    cvt_h_kernel<<<(DIM*FDIM/4  + 255)/256, 256>>>((const float4*)W2,    (__half2*)w2c, DIM*FDIM/4);
    // 1. normalize mask
    mask_kernel<<<1, 256>>>(maskraw, msk);
    // 2. LN0 (half out)
    ln_kernel<false><<<TOK, 256>>>(src, g0, beta0, ln, nullptr);
    // 3. QKV projection -> fp32 tf32-rounded (feeds tf32 attn_mma)
    gemm_mma<3*DIM, DIM, false, false, false, false, true>
        <<<dim3(3*DIM/128, TOK/128), 256, GSMEM_BYTES>>>(ln, wq, nullptr, nullptr, qkv);
    // 4. attention (tf32 tensor-core flash, half out)
    attn_mma<<<dim3(SEQ/128, BATCH*NHEAD), 256, ATTN_BYTES>>>(qkv, msk, att);
    // 5. output projection + bias + residual(src) -> x (fp32)
    gemm_mma<DIM, DIM, true, false, true, false, false>
        <<<dim3(DIM/128, TOK/128), 256, GSMEM_BYTES>>>(att, wp, bproj, src, x);
    // 6. LN1 (half out + fp32 copy for FFN residual)
    ln_kernel<true><<<TOK, 256>>>(x, g1, beta1, ln, ln32);
    // 7. FFN1 + bias + exact GELU -> half
    gemm_mma<FDIM, DIM, true, true, false, true, false>
        <<<dim3(FDIM/128, TOK/128), 256, GSMEM_BYTES>>>(ln, w1c, b1, nullptr, ffn);
    // 8. FFN2 + bias + residual(LN1 fp32) -> out (fp32)
    gemm_mma<DIM, FDIM, true, false, true, false, false>
        <<<dim3(DIM/128, TOK/128), 256, GSMEM_BYTES>>>(ffn, w2c, b2, ln32, out);
}

// round 11
// speedup vs baseline: 2.1743x; 1.1966x over previous
#include <cuda_runtime.h>
#include <cuda_fp16.h>
#include <cfloat>
#include <math.h>
#include <stdint.h>

// Problem constants
#define BATCH 8
#define SEQ   1024
#define DIM   1024
#define NHEAD 16
#define HDIM  64
#define FDIM  4096
#define TOK   (BATCH*SEQ)   // 8192

// ---------------- scratch (static device globals; no allocation) ----------------
__device__ __half g_ln  [(size_t)TOK * DIM];    // LN out (half, feeds GEMM)
__device__ float  g_ln32[(size_t)TOK * DIM];    // LN1 fp32 copy (FFN2 residual)
__device__ __half g_qkv [(size_t)TOK * 3*DIM];  // qkv (half — feeds fp16 attention)
__device__ __half g_att [(size_t)TOK * DIM];    // attention out (half)
__device__ float  g_x   [(size_t)TOK * DIM];    // src + proj(att) (fp32)
__device__ __half g_ffn [(size_t)TOK * FDIM];   // GELU(FFN1) (half)
__device__ int    g_msk [TOK];
// half weight copies
__device__ __half g_wq[(size_t)3*DIM*DIM];
__device__ __half g_wp[(size_t)DIM*DIM];
__device__ __half g_w1[(size_t)FDIM*DIM];
__device__ __half g_w2[(size_t)DIM*FDIM];

// ======================= small helpers =======================
__device__ __forceinline__ uint32_t smem_u32(const void* p) {
    uint32_t a;
    asm("{ .reg .u64 t; cvta.to.shared.u64 t, %1; cvt.u32.u64 %0, t; }" : "=r"(a) : "l"(p));
    return a;
}

__device__ __forceinline__ uint32_t h2_u32(__half2 h) {
    uint32_t u;
    memcpy(&u, &h, 4);
    return u;
}

__device__ __forceinline__ void mma_f16(float c[4],
                                        uint32_t a0, uint32_t a1, uint32_t a2, uint32_t a3,
                                        uint32_t b0, uint32_t b1) {
    asm volatile(
        "mma.sync.aligned.m16n8k16.row.col.f32.f16.f16.f32 "
        "{%0,%1,%2,%3}, {%4,%5,%6,%7}, {%8,%9}, {%0,%1,%2,%3};"
        : "+f"(c[0]), "+f"(c[1]), "+f"(c[2]), "+f"(c[3])
        : "r"(a0), "r"(a1), "r"(a2), "r"(a3), "r"(b0), "r"(b1));
}

#define LDSM_X4(r0, r1, r2, r3, addr) \
    asm volatile("ldmatrix.sync.aligned.m8n8.x4.shared.b16 {%0,%1,%2,%3}, [%4];" \
        : "=r"(r0), "=r"(r1), "=r"(r2), "=r"(r3) : "r"(addr))

#define CP_ASYNC16(saddr, gptr) \
    asm volatile("cp.async.cg.shared.global [%0], [%1], 16;" :: "r"(saddr), "l"(gptr))
#define CP_COMMIT() asm volatile("cp.async.commit_group;")
#define CP_WAIT1()  asm volatile("cp.async.wait_group 1;")
#define CP_WAIT0()  asm volatile("cp.async.wait_group 0;")

__device__ __forceinline__ float gelu_f(float x)
{
    return 0.5f * x * (1.0f + erff(x * 0.70710678118654752f));
}

// ---------------- fp32 -> fp16 weight conversion ----------------
__global__ void cvt_h_kernel(const float4* __restrict__ in, __half2* __restrict__ out, int n4)
{
    int i = blockIdx.x * blockDim.x + threadIdx.x;
    if (i < n4) {
        float4 v = in[i];
        out[2*i]   = __floats2half2_rn(v.x, v.y);
        out[2*i+1] = __floats2half2_rn(v.z, v.w);
    }
}

// ---------------- mask dtype detection + normalization ----------------
__global__ void mask_kernel(const unsigned char* __restrict__ raw, int* __restrict__ gm)
{
    __shared__ int cnt[4];
    int t = threadIdx.x;
    if (t < 4) cnt[t] = 0;
    __syncthreads();
    int l1=0, l2=0, l3=0, lb=0;
    for (int i = t; i < TOK; i += blockDim.x) {
        unsigned char bch = raw[i];
        if (bch) {
            int m = i & 3;
            if (m == 1) l1++;
            else if (m == 2) l2++;
            else if (m == 3) l3++;
            if (bch > 1) lb++;
        }
    }
    atomicAdd(&cnt[0], l1); atomicAdd(&cnt[1], l2);
    atomicAdd(&cnt[2], l3); atomicAdd(&cnt[3], lb);
    __syncthreads();
    int c1 = cnt[0], c2 = cnt[1], c3 = cnt[2], cb = cnt[3];
    int type;
    if (c1 < 64 && c2 < 64 && c3 < 64) type = 0;
    else if (c1 < 64)                  type = 1;
    else if (cb < 64)                  type = 2;
    else                               type = 3;
    for (int i = t; i < TOK; i += blockDim.x) {
        int v;
        if      (type == 0) v = (((const int*)raw)[i] != 0);
        else if (type == 1) v = (((const float*)raw)[i] != 0.0f);
        else if (type == 2) v = (raw[i] != 0);
        else                v = (((const unsigned short*)raw)[i] != 0);
        gm[i] = v;
    }
}

// ---------------- LayerNorm: half out (+ optional fp32 copy) ----------------
template<bool WF>
__global__ void ln_kernel(const float* __restrict__ in,
                          const float* __restrict__ gamma,
                          const float* __restrict__ beta,
                          __half* __restrict__ outh,
                          float* __restrict__ outf)
{
    int row = blockIdx.x;
    int t = threadIdx.x;
    const float* xr = in + (size_t)row * DIM;
    float4 v = ((const float4*)xr)[t];
    float s = v.x + v.y + v.z + v.w;
    float q = v.x*v.x + v.y*v.y + v.z*v.z + v.w*v.w;
    #pragma unroll
    for (int o = 16; o; o >>= 1) {
        s += __shfl_xor_sync(0xffffffffu, s, o);
        q += __shfl_xor_sync(0xffffffffu, q, o);
    }
    __shared__ float ss[8], qq[8];
    if ((t & 31) == 0) { ss[t >> 5] = s; qq[t >> 5] = q; }
    __syncthreads();
    s = 0.f; q = 0.f;
    #pragma unroll
    for (int i = 0; i < 8; i++) { s += ss[i]; q += qq[i]; }
    float mean = s * (1.0f / DIM);
    float var  = q * (1.0f / DIM) - mean * mean;
    float rstd = rsqrtf(var + 1e-5f);
    float4 gv = ((const float4*)gamma)[t];
    float4 bv = ((const float4*)beta)[t];
    float ox = (v.x - mean) * rstd * gv.x + bv.x;
    float oy = (v.y - mean) * rstd * gv.y + bv.y;
    float oz = (v.z - mean) * rstd * gv.z + bv.z;
    float ow = (v.w - mean) * rstd * gv.w + bv.w;
    __half2* oh = (__half2*)(outh + (size_t)row * DIM);
    oh[2*t]   = __floats2half2_rn(ox, oy);
    oh[2*t+1] = __floats2half2_rn(oz, ow);
    if (WF) {
        float4 o = {ox, oy, oz, ow};
        ((float4*)(outf + (size_t)row * DIM))[t] = o;
    }
}

// ======================= FP16 mma.sync GEMM (ldmatrix, proven in R10) =======================
#define SH2 20
#define HSTG (128*SH2)                    // half2 per matrix per stage (2560)
#define HSTG_B (HSTG*4)                   // stage stride in bytes (10240)
#define GSMEM_BYTES (4*HSTG*4)            // 40960

template<int N, int K, bool HAS_BIAS, bool HAS_GELU, bool HAS_RES, bool OUT_HALF>
__global__ void __launch_bounds__(256, 2)
gemm_mma(const __half* __restrict__ A, const __half* __restrict__ Bm,
         const float* __restrict__ bias, const float* __restrict__ res,
         void* __restrict__ Cout)
{
    extern __shared__ __half2 sh[];
    __half2* As0 = sh;
    __half2* Bs0 = sh + 2*HSTG;

    int tid  = threadIdx.x;
    int lane = tid & 31, warp = tid >> 5;
    int wm = warp >> 2, wn = warp & 3;
    int gid = lane >> 2, tig = lane & 3;
    int bm = blockIdx.y * 128, bn = blockIdx.x * 128;

    int lrow = tid >> 2;          // 0..63
    int lseg = tid & 3;           // 0..3
    const __half* gA = A  + (size_t)(bm + lrow) * K + lseg * 8;
    const __half* gB = Bm + (size_t)(bn + lrow) * K + lseg * 8;
    uint32_t sA[2], sB[2];
    #pragma unroll
    for (int st = 0; st < 2; st++) {
        sA[st] = smem_u32(&As0[st*HSTG + lrow*SH2 + lseg*4]);
        sB[st] = smem_u32(&Bs0[st*HSTG + lrow*SH2 + lseg*4]);
    }
    const uint32_t SROW64 = 64u * SH2 * 4u;
    const size_t  GROW64 = (size_t)64 * K;

    int lane15 = lane & 15;
    int lq     = lane >> 4;
    uint32_t aAddr[4];
    #pragma unroll
    for (int mt = 0; mt < 4; mt++)
        aAddr[mt] = smem_u32(&As0[(wm*64 + mt*16 + lane15)*SH2]) + lq*16;
    uint32_t bAddr[2];
    {
        int quad = lane >> 3;
        int l7   = lane & 7;
        #pragma unroll
        for (int p = 0; p < 2; p++) {
            int row = wn*32 + (2*p + (quad >> 1))*8 + l7;
            bAddr[p] = smem_u32(&Bs0[row*SH2]) + (quad & 1)*16;
        }
    }

    float acc[4][4][4];
    #pragma unroll
    for (int mt = 0; mt < 4; mt++)
        #pragma unroll
        for (int nt = 0; nt < 4; nt++)
            #pragma unroll
            for (int e = 0; e < 4; e++) acc[mt][nt][e] = 0.f;

    const int KT = K / 32;

    CP_ASYNC16(sA[0], gA); CP_ASYNC16(sA[0] + SROW64, gA + GROW64);
    CP_ASYNC16(sB[0], gB); CP_ASYNC16(sB[0] + SROW64, gB + GROW64);
    CP_COMMIT();

    for (int kt = 0; kt < KT; kt++) {
        int cur = kt & 1;
        if (kt + 1 < KT) {
            int nxt = cur ^ 1;
            size_t go = (size_t)(kt + 1) * 32;
            CP_ASYNC16(sA[nxt], gA + go); CP_ASYNC16(sA[nxt] + SROW64, gA + go + GROW64);
            CP_ASYNC16(sB[nxt], gB + go); CP_ASYNC16(sB[nxt] + SROW64, gB + go + GROW64);
            CP_COMMIT();
            CP_WAIT1();
        } else {
            CP_WAIT0();
        }
        __syncthreads();

        uint32_t stoff = (uint32_t)cur * HSTG_B;
        #pragma unroll
        for (int ks = 0; ks < 2; ks++) {
            uint32_t ko = ks * 32;
            uint32_t af[4][4];
            #pragma unroll
            for (int mt = 0; mt < 4; mt++)
                LDSM_X4(af[mt][0], af[mt][1], af[mt][2], af[mt][3],
                        aAddr[mt] + stoff + ko);
            uint32_t bf[4][2];
            #pragma unroll
            for (int p = 0; p < 2; p++)
                LDSM_X4(bf[2*p][0], bf[2*p][1], bf[2*p+1][0], bf[2*p+1][1],
                        bAddr[p] + stoff + ko);
            #pragma unroll
            for (int mt = 0; mt < 4; mt++)
                #pragma unroll
                for (int nt = 0; nt < 4; nt++)
                    mma_f16(acc[mt][nt], af[mt][0], af[mt][1], af[mt][2], af[mt][3],
                            bf[nt][0], bf[nt][1]);
        }
        __syncthreads();
    }

    #pragma unroll
    for (int mt = 0; mt < 4; mt++) {
        int row = bm + wm*64 + mt*16 + gid;
        #pragma unroll
        for (int nt = 0; nt < 4; nt++) {
            int col = bn + wn*32 + nt*8 + 2*tig;
            float2 bb = {0.f, 0.f};
            if (HAS_BIAS) bb = *(const float2*)&bias[col];
            #pragma unroll
            for (int half_ = 0; half_ < 2; half_++) {
                int rr = row + half_*8;
                float vx = acc[mt][nt][half_*2+0];
                float vy = acc[mt][nt][half_*2+1];
                if (HAS_BIAS) { vx += bb.x; vy += bb.y; }
                if (HAS_GELU) { vx = gelu_f(vx); vy = gelu_f(vy); }
                if (HAS_RES) {
                    float2 rv = *(const float2*)&res[(size_t)rr * N + col];
                    vx += rv.x; vy += rv.y;
                }
                if (OUT_HALF) {
                    __half2* cp = (__half2*)((__half*)Cout + (size_t)rr * N + col);
                    *cp = __floats2half2_rn(vx, vy);
                } else {
                    float2 o2 = {vx, vy};
                    *(float2*)((float*)Cout + (size_t)rr * N + col) = o2;
                }
            }
        }
    }
}

// ======================= fp16 flash attention (m16n8k16) — loader FIXED =======================
// 8 warps, q-tile 128 (16 q/warp), k-tile 64, D=64. half2 layout, row stride 36 half2.
#define ASQ2  0
#define ASK2  4608
#define ASV2  9216
#define ASVT2 13824
#define ASP2  16128
#define AH2TOT 20736
#define ATTN_BYTES (AH2TOT*4 + 2*64*4)   // 83456

__global__ void __launch_bounds__(256)
attn_mma(const __half* __restrict__ qkv, const int* __restrict__ gm,
         __half* __restrict__ outp)
{
    extern __shared__ __half2 S[];
    int* smk = (int*)(S + AH2TOT);

    const float SCALE = 0.125f;
    int tid = threadIdx.x, lane = tid & 31, warp = tid >> 5;
    int gid = lane >> 2, tig = lane & 3;
    int bh = blockIdx.y, b = bh >> 4, h = bh & 15;
    int q0 = blockIdx.x * 128;
    int qr = warp*16 + gid;

    // ---- stage Q tile: 128 rows x 64 halves (8 x 16B chunks per row) ----
    {
        int r = tid >> 1;
        int sg = (tid & 1) * 4;
        const __half* qp = qkv + (size_t)(b*SEQ + q0 + r) * (3*DIM) + h*HDIM;
        #pragma unroll
        for (int j = 0; j < 4; j++) {
            uint4 w = ((const uint4*)qp)[sg + j];
            *(uint4*)&S[ASQ2 + r*36 + (sg + j)*4] = w;
        }
    }

    // ---- K/V tile loader: 64 rows x 8 chunks (16B) per matrix = 512 chunks each ----
    auto issue_tile = [&](int kt, int st) {
        int tokbase = b*SEQ + kt*64;
        #pragma unroll
        for (int i = 0; i < 2; i++) {
            int c   = tid + i*256;        // 0..511
            int row = c >> 3;             // 0..63
            int seg = c & 7;              // 0..7
            const __half* kg = qkv + (size_t)(tokbase + row) * (3*DIM) + DIM + h*HDIM + seg*8;
            CP_ASYNC16(smem_u32(&S[ASK2 + st*2304 + row*36 + seg*4]), kg);
            CP_ASYNC16(smem_u32(&S[ASV2 + st*2304 + row*36 + seg*4]), kg + DIM);
        }
        if (tid < 16) {
            CP_ASYNC16(smem_u32(&smk[st*64 + tid*4]), gm + tokbase + tid*4);
        }
    };

    issue_tile(0, 0);
    CP_COMMIT();

    int mq0 = gm[b*SEQ + q0 + qr];
    int mq1 = gm[b*SEQ + q0 + qr + 8];

    float m0 = -FLT_MAX, m1 = -FLT_MAX, l0 = 0.f, l1 = 0.f;
    float acc[8][4];
    #pragma unroll
    for (int nt = 0; nt < 8; nt++)
        acc[nt][0] = acc[nt][1] = acc[nt][2] = acc[nt][3] = 0.f;

    const uint32_t* q_u  = (const uint32_t*)(S + ASQ2);
    uint32_t*       p_u  = (uint32_t*)(S + ASP2);
    const uint32_t* vt_u = (const uint32_t*)(S + ASVT2);

    for (int kt = 0; kt < 16; kt++) {
        int s = kt & 1;
        CP_WAIT0();
        __syncthreads();

        if (kt < 15) { issue_tile(kt+1, s^1); CP_COMMIT(); }

        // ---- transpose V (2x2 half2 blocks): sV[key][d] -> sVT[d][key] ----
        {
            int dp = tid & 31;       // d-pair 0..31
            int kp0 = tid >> 5;      // 0..7
            const __half2* vsrc = S + ASV2 + s*2304;
            #pragma unroll
            for (int j = 0; j < 4; j++) {
                int kp = kp0 + 8*j;
                __half2 v0 = vsrc[(2*kp)*36 + dp];
                __half2 v1 = vsrc[(2*kp+1)*36 + dp];
                S[ASVT2 + (2*dp)*36 + kp]   = __lows2half2(v0, v1);
                S[ASVT2 + (2*dp+1)*36 + kp] = __highs2half2(v0, v1);
            }
        }
        __syncthreads();

        // ---- S = Q @ K^T (4 x k16 over D=64) ----
        float sc[8][4];
        #pragma unroll
        for (int nt = 0; nt < 8; nt++)
            sc[nt][0] = sc[nt][1] = sc[nt][2] = sc[nt][3] = 0.f;
        {
            const uint32_t* k_u = (const uint32_t*)(S + ASK2 + s*2304);
            #pragma unroll
            for (int ks = 0; ks < 4; ks++) {
                int k0 = 8*ks;
                uint32_t a0 = q_u[qr*36 + tig + k0];
                uint32_t a1 = q_u[(qr+8)*36 + tig + k0];
                uint32_t a2 = q_u[qr*36 + tig + 4 + k0];
                uint32_t a3 = q_u[(qr+8)*36 + tig + 4 + k0];
                #pragma unroll
                for (int nt = 0; nt < 8; nt++) {
                    uint32_t b0 = k_u[(8*nt+gid)*36 + tig + k0];
                    uint32_t b1 = k_u[(8*nt+gid)*36 + tig + 4 + k0];
                    mma_f16(sc[nt], a0, a1, a2, a3, b0, b1);
                }
            }
        }

        // ---- mask + online softmax ----
        float mx0 = -FLT_MAX, mx1 = -FLT_MAX;
        #pragma unroll
        for (int nt = 0; nt < 8; nt++) {
            int kk = 8*nt + 2*tig;
            int ka_ = smk[s*64 + kk], kb_ = smk[s*64 + kk + 1];
            sc[nt][0] = (mq0 && ka_) ? sc[nt][0]*SCALE : -FLT_MAX;
            sc[nt][1] = (mq0 && kb_) ? sc[nt][1]*SCALE : -FLT_MAX;
            sc[nt][2] = (mq1 && ka_) ? sc[nt][2]*SCALE : -FLT_MAX;
            sc[nt][3] = (mq1 && kb_) ? sc[nt][3]*SCALE : -FLT_MAX;
            mx0 = fmaxf(mx0, fmaxf(sc[nt][0], sc[nt][1]));
            mx1 = fmaxf(mx1, fmaxf(sc[nt][2], sc[nt][3]));
        }
        mx0 = fmaxf(mx0, __shfl_xor_sync(0xffffffffu, mx0, 1));
        mx0 = fmaxf(mx0, __shfl_xor_sync(0xffffffffu, mx0, 2));
        mx1 = fmaxf(mx1, __shfl_xor_sync(0xffffffffu, mx1, 1));
        mx1 = fmaxf(mx1, __shfl_xor_sync(0xffffffffu, mx1, 2));

        float mn0 = fmaxf(m0, mx0), mn1 = fmaxf(m1, mx1);
        float c0 = __expf(m0 - mn0), c1 = __expf(m1 - mn1);
        float ps0 = 0.f, ps1 = 0.f;
        #pragma unroll
        for (int nt = 0; nt < 8; nt++) {
            float p00 = __expf(sc[nt][0] - mn0);
            float p01 = __expf(sc[nt][1] - mn0);
            float p10 = __expf(sc[nt][2] - mn1);
            float p11 = __expf(sc[nt][3] - mn1);
            ps0 += p00 + p01; ps1 += p10 + p11;
            int cp = 4*nt + tig;             // half2 col index
            p_u[qr*36 + cp]     = h2_u32(__floats2half2_rn(p00, p01));
            p_u[(qr+8)*36 + cp] = h2_u32(__floats2half2_rn(p10, p11));
        }
        ps0 += __shfl_xor_sync(0xffffffffu, ps0, 1);
        ps0 += __shfl_xor_sync(0xffffffffu, ps0, 2);
        ps1 += __shfl_xor_sync(0xffffffffu, ps1, 1);
        ps1 += __shfl_xor_sync(0xffffffffu, ps1, 2);
        l0 = l0*c0 + ps0; l1 = l1*c1 + ps1;
        m0 = mn0; m1 = mn1;
        #pragma unroll
        for (int nt = 0; nt < 8; nt++) {
            acc[nt][0] *= c0; acc[nt][1] *= c0;
            acc[nt][2] *= c1; acc[nt][3] *= c1;
        }
        __syncwarp();

        // ---- O += P @ V^T (4 x k16 over 64 keys) ----
        #pragma unroll
        for (int ks = 0; ks < 4; ks++) {
            int k0 = 8*ks;
            uint32_t a0 = p_u[qr*36 + tig + k0];
            uint32_t a1 = p_u[(qr+8)*36 + tig + k0];
            uint32_t a2 = p_u[qr*36 + tig + 4 + k0];
            uint32_t a3 = p_u[(qr+8)*36 + tig + 4 + k0];
            #pragma unroll
            for (int nt = 0; nt < 8; nt++) {
                uint32_t b0 = vt_u[(8*nt+gid)*36 + tig + k0];
                uint32_t b1 = vt_u[(8*nt+gid)*36 + tig + 4 + k0];
                mma_f16(acc[nt], a0, a1, a2, a3, b0, b1);
            }
        }
    }

    // ---- epilogue: /l, store half ----
    float inv0 = 1.0f / l0, inv1 = 1.0f / l1;
    __half2* op0 = (__half2*)(outp + (size_t)(b*SEQ + q0 + qr) * DIM + h*HDIM);
    __half2* op1 = (__half2*)(outp + (size_t)(b*SEQ + q0 + qr + 8) * DIM + h*HDIM);
    #pragma unroll
    for (int nt = 0; nt < 8; nt++) {
        int cp = 4*nt + tig;
        op0[cp] = __floats2half2_rn(acc[nt][0]*inv0, acc[nt][1]*inv0);
        op1[cp] = __floats2half2_rn(acc[nt][2]*inv1, acc[nt][3]*inv1);
    }
}

// ======================= host side =======================
extern "C" void kernel_launch(void* const* d_in, const int* in_sizes, int n_in,
                              void* d_out, int out_size)
{
    const float* src   = (const float*)d_in[0];
    const unsigned char* maskraw = (const unsigned char*)d_in[1];
    const float* Wqkv  = (const float*)d_in[2];
    const float* Wproj = (const float*)d_in[3];
    const float* bproj = (const float*)d_in[4];
    const float* W1    = (const float*)d_in[5];
    const float* b1    = (const float*)d_in[6];
    const float* W2    = (const float*)d_in[7];
    const float* b2    = (const float*)d_in[8];
    const float* g0    = (const float*)d_in[9];
    const float* beta0 = (const float*)d_in[10];
    const float* g1    = (const float*)d_in[11];
    const float* beta1 = (const float*)d_in[12];
    float* out = (float*)d_out;

    __half *ln, *qkv, *att, *ffn, *wq, *wp, *w1c, *w2c;
    float *ln32, *x; int* msk;
    cudaGetSymbolAddress((void**)&ln,   g_ln);
    cudaGetSymbolAddress((void**)&ln32, g_ln32);
    cudaGetSymbolAddress((void**)&qkv,  g_qkv);
    cudaGetSymbolAddress((void**)&att,  g_att);
    cudaGetSymbolAddress((void**)&x,    g_x);
    cudaGetSymbolAddress((void**)&ffn,  g_ffn);
    cudaGetSymbolAddress((void**)&msk,  g_msk);
    cudaGetSymbolAddress((void**)&wq,   g_wq);
    cudaGetSymbolAddress((void**)&wp,   g_wp);
    cudaGetSymbolAddress((void**)&w1c,  g_w1);
    cudaGetSymbolAddress((void**)&w2c,  g_w2);

    cudaFuncSetAttribute(attn_mma, cudaFuncAttributeMaxDynamicSharedMemorySize, ATTN_BYTES);

    // 0. weights -> fp16
    cvt_h_kernel<<<(3*DIM*DIM/4 + 255)/256, 256>>>((const float4*)Wqkv,  (__half2*)wq,  3*DIM*DIM/4);
    cvt_h_kernel<<<(DIM*DIM/4   + 255)/256, 256>>>((const float4*)Wproj, (__half2*)wp,  DIM*DIM/4);
    cvt_h_kernel<<<(FDIM*DIM/4  + 255)/256, 256>>>((const float4*)W1,    (__half2*)w1c, FDIM*DIM/4);
    cvt_h_kernel<<<(DIM*FDIM/4  + 255)/256, 256>>>((const float4*)W2,    (__half2*)w2c, DIM*FDIM/4);
    // 1. normalize mask
    mask_kernel<<<1, 256>>>(maskraw, msk);
    // 2. LN0 (half out)
    ln_kernel<false><<<TOK, 256>>>(src, g0, beta0, ln, nullptr);
    // 3. QKV projection -> half (feeds fp16 attention)
    gemm_mma<3*DIM, DIM, false, false, false, true>
        <<<dim3(3*DIM/128, TOK/128), 256, GSMEM_BYTES>>>(ln, wq, nullptr, nullptr, qkv);
    // 4. attention (fp16 tensor-core flash, half out)
    attn_mma<<<dim3(SEQ/128, BATCH*NHEAD), 256, ATTN_BYTES>>>(qkv, msk, att);
    // 5. output projection + bias + residual(src) -> x (fp32)
    gemm_mma<DIM, DIM, true, false, true, false>
        <<<dim3(DIM/128, TOK/128), 256, GSMEM_BYTES>>>(att, wp, bproj, src, x);
    // 6. LN1 (half out + fp32 copy for FFN residual)
    ln_kernel<true><<<TOK, 256>>>(x, g1, beta1, ln, ln32);
    // 7. FFN1 + bias + exact GELU -> half
    gemm_mma<FDIM, DIM, true, true, false, true>
        <<<dim3(FDIM/128, TOK/128), 256, GSMEM_BYTES>>>(ln, w1c, b1, nullptr, ffn);
    // 8. FFN2 + bias + residual(LN1 fp32) -> out (fp32)
    gemm_mma<DIM, FDIM, true, false, true, false>
        <<<dim3(DIM/128, TOK/128), 256, GSMEM_BYTES>>>(ffn, w2c, b2, ln32, out);
}